// round 9
// baseline (speedup 1.0000x reference)
#include <cuda_runtime.h>
#include <cuda_fp16.h>
#include <cstdint>

#define N_NODES 65536
#define N_EDGES 1048576
#define EMB 64
#define IN_DIM 128
#define OUT_DIM 32
#define N_HIDDEN 4
#define N_CHUNKS 1024   // 65536 / 64

// ---------------- scratch (static device globals; no allocation) ----------------
__device__ float  g_h[N_NODES * EMB];        // layer activations (fp32)
__device__ __half g_hw16[N_NODES * EMB];     // post-GEMM messages (fp16 payload)
__device__ float  g_dinv[N_NODES];           // 1/sqrt(deg)
__device__ float  g_deg[N_NODES];            // weighted in-degree (atomic float)
__device__ int    g_count[N_NODES];          // in-degree histogram
__device__ int    g_rowptr[N_NODES + 1];     // CSR row pointers (by dst)
__device__ int    g_work[N_NODES];           // fill cursors (copy of rowptr)
__device__ int2   g_csr[N_EDGES];            // CSR: {src, float_bits(norm_w)}
__device__ int    g_choff[N_CHUNKS];         // exclusive chunk offsets
__device__ int    g_part[N_CHUNKS];          // chunk partial sums
__device__ int    g_is64;                    // edge_index dtype flag

// ---------------- packed f32x2 helpers (Blackwell) ----------------
__device__ __forceinline__ unsigned long long pk2(float lo, float hi) {
    unsigned long long r;
    asm("mov.b64 %0, {%1, %2};" : "=l"(r) : "f"(lo), "f"(hi));
    return r;
}
__device__ __forceinline__ void fma2(unsigned long long& acc,
                                     unsigned long long a, unsigned long long b) {
    asm("fma.rn.f32x2 %0, %1, %2, %0;" : "+l"(acc) : "l"(a), "l"(b));
}
__device__ __forceinline__ float2 unpk(unsigned long long v) {
    float2 f;
    asm("mov.b64 {%0, %1}, %2;" : "=f"(f.x), "=f"(f.y) : "l"(v));
    return f;
}

// ---------------- dtype detection ----------------
__global__ void detect_kernel(const unsigned int* __restrict__ w) {
    __shared__ int s_any;
    if (threadIdx.x == 0) s_any = 0;
    __syncthreads();
    unsigned int v = w[2 * threadIdx.x + 1];
    if (v != 0) s_any = 1;
    __syncthreads();
    if (threadIdx.x == 0) g_is64 = (s_any == 0) ? 1 : 0;
}

__device__ __forceinline__ int load_idx(const void* p, int i) {
    if (g_is64) return (int)((const long long*)p)[i];
    return ((const int*)p)[i];
}

// ---------------- pass 1: count + weighted degree ----------------
__global__ void count_deg_kernel(const void* __restrict__ eidx,
                                 const float* __restrict__ ew) {
    int e = blockIdx.x * blockDim.x + threadIdx.x;
    if (e >= N_EDGES) return;
    int dst = load_idx(eidx, N_EDGES + e);
    atomicAdd(&g_count[dst], 1);
    atomicAdd(&g_deg[dst], ew[e]);
}

// ---------------- scan phase 1 ----------------
__global__ void chunk_reduce_kernel() {
    int warp = (blockIdx.x * blockDim.x + threadIdx.x) >> 5;
    int lane = threadIdx.x & 31;
    if (warp >= N_CHUNKS) return;
    int base = warp * 64;
    int v = g_count[base + lane] + g_count[base + 32 + lane];
#pragma unroll
    for (int off = 16; off > 0; off >>= 1)
        v += __shfl_down_sync(0xffffffffu, v, off);
    if (lane == 0) g_part[warp] = v;
}

// ---------------- scan phase 2 ----------------
__global__ void scan_part_kernel() {
    __shared__ int s[N_CHUNKS];
    int t = threadIdx.x;
    int orig = g_part[t];
    s[t] = orig;
    __syncthreads();
    for (int off = 1; off < N_CHUNKS; off <<= 1) {
        int v = (t >= off) ? s[t - off] : 0;
        __syncthreads();
        s[t] += v;
        __syncthreads();
    }
    g_choff[t] = s[t] - orig;  // exclusive
}

// ---------------- scan phase 3: rowptr + work + dinv ----------------
__global__ void rowptr_dinv_kernel() {
    int warp = (blockIdx.x * blockDim.x + threadIdx.x) >> 5;
    int lane = threadIdx.x & 31;
    if (warp >= N_CHUNKS) return;
    int base = warp * 64;
    int c0 = g_count[base + lane];
    int c1 = g_count[base + 32 + lane];
    int i0 = c0, i1 = c1;
#pragma unroll
    for (int off = 1; off < 32; off <<= 1) {
        int v0 = __shfl_up_sync(0xffffffffu, i0, off);
        int v1 = __shfl_up_sync(0xffffffffu, i1, off);
        if (lane >= off) { i0 += v0; i1 += v1; }
    }
    int tot0 = __shfl_sync(0xffffffffu, i0, 31);
    int off = g_choff[warp];
    int r0 = off + i0 - c0;
    int r1 = off + tot0 + i1 - c1;
    g_rowptr[base + lane] = r0;
    g_rowptr[base + 32 + lane] = r1;
    g_work[base + lane] = r0;
    g_work[base + 32 + lane] = r1;
    if (warp == N_CHUNKS - 1 && lane == 31) g_rowptr[N_NODES] = N_EDGES;
    float d, r;
    d = 1.0f + g_deg[base + lane];
    r = rsqrtf(d);
    g_dinv[base + lane] = r * (1.5f - 0.5f * d * r * r);
    d = 1.0f + g_deg[base + 32 + lane];
    r = rsqrtf(d);
    g_dinv[base + 32 + lane] = r * (1.5f - 0.5f * d * r * r);
}

// ---------------- fill CSR with normalized weights ----------------
__global__ void fill_kernel(const void* __restrict__ eidx,
                            const float* __restrict__ ew) {
    int e = blockIdx.x * blockDim.x + threadIdx.x;
    if (e >= N_EDGES) return;
    int src = load_idx(eidx, e);
    int dst = load_idx(eidx, N_EDGES + e);
    float w = ew[e] * g_dinv[src] * g_dinv[dst];
    int pos = atomicAdd(&g_work[dst], 1);
    g_csr[pos] = make_int2(src, __float_as_int(w));
}

// ---------------- GEMM -> fp16: C16[N_NODES,64] = A[N_NODES,K] @ W[K,64] ----------------
// 128-row x 64-col block tile, 256 threads, thread = 8 rows x 4 cols.
// Accumulators packed as row-pairs in f32x2 so A operands fall out of LDS.128 quads.
template <int K>
__global__ __launch_bounds__(256) void gemm128_h_kernel(
    const float* __restrict__ A, const float* __restrict__ W,
    __half* __restrict__ C16) {
    __shared__ float As[64 * 128];   // 32KB: As[k][r] (transposed)
    __shared__ float Ws[64 * 64];    // 16KB: Ws[k][c]
    int tid = threadIdx.x;
    int tx = tid & 15, ty = tid >> 4;   // tx: col group (4 cols), ty: row group (8 rows)
    int row0 = blockIdx.x * 128;

    // acc[rp][c]: f32x2 over row-pair (2*rp, 2*rp+1), col c
    unsigned long long acc[4][4];
#pragma unroll
    for (int rp = 0; rp < 4; rp++)
#pragma unroll
        for (int c = 0; c < 4; c++) acc[rp][c] = 0ULL;

    for (int kc = 0; kc < K; kc += 64) {
        __syncthreads();
        for (int i = tid; i < 128 * 64; i += 256) {
            int r = i >> 6, k = i & 63;
            As[k * 128 + r] = A[(size_t)(row0 + r) * K + kc + k];
        }
        for (int i = tid; i < 64 * 64; i += 256) {
            int k = i >> 6, c = i & 63;
            Ws[k * 64 + c] = W[(size_t)(kc + k) * 64 + c];
        }
        __syncthreads();
#pragma unroll 8
        for (int k = 0; k < 64; k++) {
            float4 alo = *(const float4*)&As[k * 128 + ty * 8];
            float4 ahi = *(const float4*)&As[k * 128 + ty * 8 + 4];
            float4 w = *(const float4*)&Ws[k * 64 + tx * 4];
            unsigned long long arp[4] = {
                pk2(alo.x, alo.y), pk2(alo.z, alo.w),
                pk2(ahi.x, ahi.y), pk2(ahi.z, ahi.w)};
            unsigned long long wb[4] = {
                pk2(w.x, w.x), pk2(w.y, w.y), pk2(w.z, w.z), pk2(w.w, w.w)};
#pragma unroll
            for (int rp = 0; rp < 4; rp++) {
                fma2(acc[rp][0], arp[rp], wb[0]);
                fma2(acc[rp][1], arp[rp], wb[1]);
                fma2(acc[rp][2], arp[rp], wb[2]);
                fma2(acc[rp][3], arp[rp], wb[3]);
            }
        }
    }
    // epilogue: convert to fp16, 4 cols per row -> one uint2 store per row
#pragma unroll
    for (int rp = 0; rp < 4; rp++) {
        float2 v0 = unpk(acc[rp][0]);
        float2 v1 = unpk(acc[rp][1]);
        float2 v2 = unpk(acc[rp][2]);
        float2 v3 = unpk(acc[rp][3]);
        int re = row0 + ty * 8 + 2 * rp;      // even row
        __half2 e01 = __floats2half2_rn(v0.x, v1.x);
        __half2 e23 = __floats2half2_rn(v2.x, v3.x);
        __half2 o01 = __floats2half2_rn(v0.y, v1.y);
        __half2 o23 = __floats2half2_rn(v2.y, v3.y);
        uint2 ue, uo;
        ue.x = *(unsigned*)&e01; ue.y = *(unsigned*)&e23;
        uo.x = *(unsigned*)&o01; uo.y = *(unsigned*)&o23;
        ((uint2*)C16)[(size_t)re * 16 + tx] = ue;
        ((uint2*)C16)[(size_t)(re + 1) * 16 + tx] = uo;
    }
}

// ---------------- aggregation (fp16 gather) + bias + ELU ----------------
// Warp per node, R4 structure. Row = 64 halves = 16 uint2; half-warp (16 lanes
// x uint2=4 halves) covers one row -> warp gathers 2 edges/iter, LDG.64 per lane.
__global__ __launch_bounds__(256) void agg_elu_kernel(
    const __half* __restrict__ hw16, const float* __restrict__ bias) {
    int node = (blockIdx.x * blockDim.x + threadIdx.x) >> 5;
    int lane = threadIdx.x & 31;
    if (node >= N_NODES) return;
    int half = lane >> 4;     // 0 or 1
    int l16 = lane & 15;
    const uint2* hw2 = (const uint2*)hw16;  // row = 16 uint2
    float4 acc = make_float4(0.f, 0.f, 0.f, 0.f);
    if (half == 0) {
        float di = g_dinv[node];
        float ws = di * di;
        uint2 u = hw2[(size_t)node * 16 + l16];
        float2 f0 = __half22float2(*(const __half2*)&u.x);
        float2 f1 = __half22float2(*(const __half2*)&u.y);
        acc.x = ws * f0.x; acc.y = ws * f0.y; acc.z = ws * f1.x; acc.w = ws * f1.y;
    }
    int s0 = g_rowptr[node], s1 = g_rowptr[node + 1];
    for (int e = s0; e < s1; e += 2) {
        int ee = e + half;
        int2 m = (ee < s1) ? g_csr[ee] : make_int2(0, 0);  // pad: w = 0.0f
        float w = __int_as_float(m.y);
        uint2 u = hw2[(size_t)m.x * 16 + l16];
        float2 f0 = __half22float2(*(const __half2*)&u.x);
        float2 f1 = __half22float2(*(const __half2*)&u.y);
        acc.x = fmaf(w, f0.x, acc.x);
        acc.y = fmaf(w, f0.y, acc.y);
        acc.z = fmaf(w, f1.x, acc.z);
        acc.w = fmaf(w, f1.y, acc.w);
    }
    acc.x += __shfl_down_sync(0xffffffffu, acc.x, 16);
    acc.y += __shfl_down_sync(0xffffffffu, acc.y, 16);
    acc.z += __shfl_down_sync(0xffffffffu, acc.z, 16);
    acc.w += __shfl_down_sync(0xffffffffu, acc.w, 16);
    if (half == 0) {
        float4 bb = ((const float4*)bias)[l16];
        acc.x += bb.x; acc.y += bb.y; acc.z += bb.z; acc.w += bb.w;
        acc.x = acc.x > 0.f ? acc.x : expm1f(acc.x);
        acc.y = acc.y > 0.f ? acc.y : expm1f(acc.y);
        acc.z = acc.z > 0.f ? acc.z : expm1f(acc.z);
        acc.w = acc.w > 0.f ? acc.w : expm1f(acc.w);
        ((float4*)g_h)[(size_t)node * 16 + l16] = acc;
    }
}

// ---------------- final linear 64->32 + bias + ReLU (proven R7 kernel) ----------------
__global__ __launch_bounds__(256) void final_gemm_kernel(
    const float* __restrict__ A, const float* __restrict__ W,
    const float* __restrict__ bias, float* __restrict__ C) {
    constexpr int AP = 68;
    __shared__ float As[64 * AP];
    __shared__ float Ws[64 * OUT_DIM];
    int tid = threadIdx.x;
    int tx = tid & 15, ty = tid >> 4;
    int row0 = blockIdx.x * 64;
    unsigned long long acc[4];
#pragma unroll
    for (int r = 0; r < 4; r++) acc[r] = 0ULL;
    for (int i = tid; i < 64 * 64; i += 256) {
        int r = i >> 6, k = i & 63;
        As[k * AP + r] = A[(size_t)(row0 + r) * 64 + k];
    }
    for (int i = tid; i < 64 * OUT_DIM; i += 256) {
        int k = i / OUT_DIM, c = i % OUT_DIM;
        Ws[k * OUT_DIM + c] = W[(size_t)k * OUT_DIM + c];
    }
    __syncthreads();
#pragma unroll 8
    for (int k = 0; k < 64; k++) {
        float4 a = *(const float4*)&As[k * AP + ty * 4];
        unsigned long long a0 = pk2(a.x, a.x), a1 = pk2(a.y, a.y);
        unsigned long long a2 = pk2(a.z, a.z), a3 = pk2(a.w, a.w);
        float2 w = *(const float2*)&Ws[k * OUT_DIM + tx * 2];
        unsigned long long w01 = pk2(w.x, w.y);
        fma2(acc[0], a0, w01);
        fma2(acc[1], a1, w01);
        fma2(acc[2], a2, w01);
        fma2(acc[3], a3, w01);
    }
#pragma unroll
    for (int r = 0; r < 4; r++) {
        int row = row0 + ty * 4 + r;
        float2 p = unpk(acc[r]);
        p.x += bias[tx * 2];
        p.y += bias[tx * 2 + 1];
        p.x = p.x > 0.f ? p.x : 0.f;
        p.y = p.y > 0.f ? p.y : 0.f;
        *(float2*)&C[(size_t)row * OUT_DIM + tx * 2] = p;
    }
}

// ---------------- launch ----------------
extern "C" void kernel_launch(void* const* d_in, const int* in_sizes, int n_in,
                              void* d_out, int out_size) {
    const float* x      = (const float*)d_in[0];
    const void*  eidx   = d_in[1];
    const float* ew     = (const float*)d_in[2];
    const float* W1     = (const float*)d_in[3];
    const float* b1     = (const float*)d_in[4];
    const float* W_hid  = (const float*)d_in[5];
    const float* b_hid  = (const float*)d_in[6];
    const float* W_lin  = (const float*)d_in[7];
    const float* b_lin  = (const float*)d_in[8];
    float* out = (float*)d_out;

    float* h_ptr;
    __half* hw16_ptr;
    void *count_ptr, *deg_ptr;
    cudaGetSymbolAddress((void**)&h_ptr, g_h);
    cudaGetSymbolAddress((void**)&hw16_ptr, g_hw16);
    cudaGetSymbolAddress(&count_ptr, g_count);
    cudaGetSymbolAddress(&deg_ptr, g_deg);

    // ---- preprocessing + layer-1 GEMM interleaved; launch idx 5 = gemm1 (ncu target) ----
    detect_kernel<<<1, 128>>>((const unsigned int*)eidx);            // 0
    cudaMemsetAsync(count_ptr, 0, N_NODES * sizeof(int));            // 1
    cudaMemsetAsync(deg_ptr, 0, N_NODES * sizeof(float));            // 2
    count_deg_kernel<<<N_EDGES / 256, 256>>>(eidx, ew);              // 3
    chunk_reduce_kernel<<<N_CHUNKS / 8, 256>>>();                    // 4
    gemm128_h_kernel<IN_DIM><<<N_NODES / 128, 256>>>(x, W1, hw16_ptr); // 5 <- profiled
    scan_part_kernel<<<1, N_CHUNKS>>>();                             // 6
    rowptr_dinv_kernel<<<N_CHUNKS / 8, 256>>>();                     // 7
    fill_kernel<<<N_EDGES / 256, 256>>>(eidx, ew);                   // 8

    // ---- layer 1 aggregation ----
    agg_elu_kernel<<<N_NODES / 8, 256>>>(hw16_ptr, b1);              // 9

    // ---- hidden layers: 64 -> 64 ----
    for (int l = 0; l < N_HIDDEN; l++) {
        gemm128_h_kernel<EMB><<<N_NODES / 128, 256>>>(
            h_ptr, W_hid + (size_t)l * EMB * EMB, hw16_ptr);
        agg_elu_kernel<<<N_NODES / 8, 256>>>(hw16_ptr, b_hid + (size_t)l * EMB);
    }

    // ---- final linear 64 -> 32 + bias + ReLU ----
    final_gemm_kernel<<<N_NODES / 64, 256>>>(h_ptr, W_lin, b_lin, out);
}

// round 12
// speedup vs baseline: 1.1329x; 1.1329x over previous
#include <cuda_runtime.h>
#include <cuda_fp16.h>
#include <cstdint>

#define N_NODES 65536
#define N_EDGES 1048576
#define EMB 64
#define IN_DIM 128
#define OUT_DIM 32
#define N_HIDDEN 4
#define N_CHUNKS 1024   // 65536 / 64

// ---------------- scratch (static device globals; no allocation) ----------------
__device__ float  g_h[N_NODES * EMB];        // layer activations (fp32)
__device__ __half g_hw16[N_NODES * EMB];     // post-GEMM messages (fp16 payload)
__device__ float  g_dinv[N_NODES];           // 1/sqrt(deg)
__device__ float  g_deg[N_NODES];            // weighted in-degree (atomic float)
__device__ int    g_count[N_NODES];          // in-degree histogram
__device__ int    g_rowptr[N_NODES + 1];     // CSR row pointers (by dst)
__device__ int    g_work[N_NODES];           // fill cursors (copy of rowptr)
__device__ int2   g_csr[N_EDGES];            // CSR: {src, float_bits(norm_w)}
__device__ int    g_choff[N_CHUNKS];         // exclusive chunk offsets
__device__ int    g_part[N_CHUNKS];          // chunk partial sums
__device__ int    g_is64;                    // edge_index dtype flag

// ---------------- packed f32x2 helpers (Blackwell) ----------------
__device__ __forceinline__ void fma2(unsigned long long& acc,
                                     unsigned long long a, unsigned long long b) {
    asm("fma.rn.f32x2 %0, %1, %2, %0;" : "+l"(acc) : "l"(a), "l"(b));
}
__device__ __forceinline__ unsigned long long pk2(float lo, float hi) {
    unsigned long long r;
    asm("mov.b64 %0, {%1, %2};" : "=l"(r) : "f"(lo), "f"(hi));
    return r;
}
__device__ __forceinline__ float2 unpk(unsigned long long v) {
    float2 f;
    asm("mov.b64 {%0, %1}, %2;" : "=f"(f.x), "=f"(f.y) : "l"(v));
    return f;
}

// ---------------- dtype detection ----------------
__global__ void detect_kernel(const unsigned int* __restrict__ w) {
    __shared__ int s_any;
    if (threadIdx.x == 0) s_any = 0;
    __syncthreads();
    unsigned int v = w[2 * threadIdx.x + 1];
    if (v != 0) s_any = 1;
    __syncthreads();
    if (threadIdx.x == 0) g_is64 = (s_any == 0) ? 1 : 0;
}

__device__ __forceinline__ int load_idx(const void* p, int i) {
    if (g_is64) return (int)((const long long*)p)[i];
    return ((const int*)p)[i];
}

// ---------------- pass 1: count + weighted degree ----------------
__global__ void count_deg_kernel(const void* __restrict__ eidx,
                                 const float* __restrict__ ew) {
    int e = blockIdx.x * blockDim.x + threadIdx.x;
    if (e >= N_EDGES) return;
    int dst = load_idx(eidx, N_EDGES + e);
    atomicAdd(&g_count[dst], 1);
    atomicAdd(&g_deg[dst], ew[e]);
}

// ---------------- scan phase 1 ----------------
__global__ void chunk_reduce_kernel() {
    int warp = (blockIdx.x * blockDim.x + threadIdx.x) >> 5;
    int lane = threadIdx.x & 31;
    if (warp >= N_CHUNKS) return;
    int base = warp * 64;
    int v = g_count[base + lane] + g_count[base + 32 + lane];
#pragma unroll
    for (int off = 16; off > 0; off >>= 1)
        v += __shfl_down_sync(0xffffffffu, v, off);
    if (lane == 0) g_part[warp] = v;
}

// ---------------- scan phase 2 ----------------
__global__ void scan_part_kernel() {
    __shared__ int s[N_CHUNKS];
    int t = threadIdx.x;
    int orig = g_part[t];
    s[t] = orig;
    __syncthreads();
    for (int off = 1; off < N_CHUNKS; off <<= 1) {
        int v = (t >= off) ? s[t - off] : 0;
        __syncthreads();
        s[t] += v;
        __syncthreads();
    }
    g_choff[t] = s[t] - orig;  // exclusive
}

// ---------------- scan phase 3: rowptr + work + dinv ----------------
__global__ void rowptr_dinv_kernel() {
    int warp = (blockIdx.x * blockDim.x + threadIdx.x) >> 5;
    int lane = threadIdx.x & 31;
    if (warp >= N_CHUNKS) return;
    int base = warp * 64;
    int c0 = g_count[base + lane];
    int c1 = g_count[base + 32 + lane];
    int i0 = c0, i1 = c1;
#pragma unroll
    for (int off = 1; off < 32; off <<= 1) {
        int v0 = __shfl_up_sync(0xffffffffu, i0, off);
        int v1 = __shfl_up_sync(0xffffffffu, i1, off);
        if (lane >= off) { i0 += v0; i1 += v1; }
    }
    int tot0 = __shfl_sync(0xffffffffu, i0, 31);
    int off = g_choff[warp];
    int r0 = off + i0 - c0;
    int r1 = off + tot0 + i1 - c1;
    g_rowptr[base + lane] = r0;
    g_rowptr[base + 32 + lane] = r1;
    g_work[base + lane] = r0;
    g_work[base + 32 + lane] = r1;
    if (warp == N_CHUNKS - 1 && lane == 31) g_rowptr[N_NODES] = N_EDGES;
    float d, r;
    d = 1.0f + g_deg[base + lane];
    r = rsqrtf(d);
    g_dinv[base + lane] = r * (1.5f - 0.5f * d * r * r);
    d = 1.0f + g_deg[base + 32 + lane];
    r = rsqrtf(d);
    g_dinv[base + 32 + lane] = r * (1.5f - 0.5f * d * r * r);
}

// ---------------- fill CSR with normalized weights ----------------
__global__ void fill_kernel(const void* __restrict__ eidx,
                            const float* __restrict__ ew) {
    int e = blockIdx.x * blockDim.x + threadIdx.x;
    if (e >= N_EDGES) return;
    int src = load_idx(eidx, e);
    int dst = load_idx(eidx, N_EDGES + e);
    float w = ew[e] * g_dinv[src] * g_dinv[dst];
    int pos = atomicAdd(&g_work[dst], 1);
    g_csr[pos] = make_int2(src, __float_as_int(w));
}

// ---------------- GEMM -> fp16: C16[N_NODES,64] = A[N_NODES,K] @ W[K,64] ----------------
// 64x64 tile, 256 threads, thread = 4 rows x 4 cols.
// k-pair f32x2 accumulators: acc.x sums even k, acc.y odd k; folded in epilogue.
// A row-major in smem (pad 68) -> LDS.64 gives the (k, k+1) operand pair free.
// W stored k-pair-interleaved: Ws2[kp*128 + c*2 + (k&1)] -> ulonglong2 LDS gives
// W pairs for 2 cols free. Zero packing MOVs, conflict-free smem.
template <int K>
__global__ __launch_bounds__(256) void gemm_pair_kernel(
    const float* __restrict__ A, const float* __restrict__ W,
    __half* __restrict__ C16) {
    __shared__ float As[64 * 68];    // 17.4KB, row-major
    __shared__ float Ws2[64 * 64];   // 16KB, pair-interleaved
    int tid = threadIdx.x;
    int tx = tid & 15, ty = tid >> 4;
    int row0 = blockIdx.x * 64;

    unsigned long long acc[4][4];
#pragma unroll
    for (int r = 0; r < 4; r++)
#pragma unroll
        for (int c = 0; c < 4; c++) acc[r][c] = 0ULL;

    for (int kc = 0; kc < K; kc += 64) {
        __syncthreads();
        // A tile: float4 GMEM loads -> float4 row-major STS (conflict-free)
#pragma unroll
        for (int i = tid; i < 64 * 16; i += 256) {
            int r = i >> 4, f = i & 15;
            float4 v = *(const float4*)&A[(size_t)(row0 + r) * K + kc + f * 4];
            *(float4*)&As[r * 68 + f * 4] = v;
        }
        // W chunk: scatter into pair-interleaved layout
#pragma unroll
        for (int i = tid; i < 64 * 16; i += 256) {
            int k = i >> 4, cg = i & 15;
            float4 v = *(const float4*)&W[(size_t)(kc + k) * 64 + cg * 4];
            int base = (k >> 1) * 128 + (k & 1);
            Ws2[base + (cg * 4 + 0) * 2] = v.x;
            Ws2[base + (cg * 4 + 1) * 2] = v.y;
            Ws2[base + (cg * 4 + 2) * 2] = v.z;
            Ws2[base + (cg * 4 + 3) * 2] = v.w;
        }
        __syncthreads();
#pragma unroll 4
        for (int kp = 0; kp < 32; kp++) {
            unsigned long long a0 = *(const unsigned long long*)&As[(ty * 4 + 0) * 68 + kp * 2];
            unsigned long long a1 = *(const unsigned long long*)&As[(ty * 4 + 1) * 68 + kp * 2];
            unsigned long long a2 = *(const unsigned long long*)&As[(ty * 4 + 2) * 68 + kp * 2];
            unsigned long long a3 = *(const unsigned long long*)&As[(ty * 4 + 3) * 68 + kp * 2];
            ulonglong2 wl = *(const ulonglong2*)&Ws2[kp * 128 + tx * 8];      // cols c0,c1
            ulonglong2 wh = *(const ulonglong2*)&Ws2[kp * 128 + tx * 8 + 4];  // cols c2,c3
            fma2(acc[0][0], a0, wl.x); fma2(acc[0][1], a0, wl.y);
            fma2(acc[0][2], a0, wh.x); fma2(acc[0][3], a0, wh.y);
            fma2(acc[1][0], a1, wl.x); fma2(acc[1][1], a1, wl.y);
            fma2(acc[1][2], a1, wh.x); fma2(acc[1][3], a1, wh.y);
            fma2(acc[2][0], a2, wl.x); fma2(acc[2][1], a2, wl.y);
            fma2(acc[2][2], a2, wh.x); fma2(acc[2][3], a2, wh.y);
            fma2(acc[3][0], a3, wl.x); fma2(acc[3][1], a3, wl.y);
            fma2(acc[3][2], a3, wh.x); fma2(acc[3][3], a3, wh.y);
        }
    }
    // epilogue: fold (even,odd) halves, convert to fp16, one uint2 store per row
#pragma unroll
    for (int r = 0; r < 4; r++) {
        float2 p0 = unpk(acc[r][0]);
        float2 p1 = unpk(acc[r][1]);
        float2 p2 = unpk(acc[r][2]);
        float2 p3 = unpk(acc[r][3]);
        float v0 = p0.x + p0.y, v1 = p1.x + p1.y;
        float v2 = p2.x + p2.y, v3 = p3.x + p3.y;
        int row = row0 + ty * 4 + r;
        __half2 h01 = __floats2half2_rn(v0, v1);
        __half2 h23 = __floats2half2_rn(v2, v3);
        uint2 u;
        u.x = *(unsigned*)&h01;
        u.y = *(unsigned*)&h23;
        ((uint2*)C16)[(size_t)row * 16 + tx] = u;
    }
}

// ---------------- aggregation (fp16 gather) + bias + ELU (R9 version) ----------------
__global__ __launch_bounds__(256) void agg_elu_kernel(
    const __half* __restrict__ hw16, const float* __restrict__ bias) {
    int node = (blockIdx.x * blockDim.x + threadIdx.x) >> 5;
    int lane = threadIdx.x & 31;
    if (node >= N_NODES) return;
    int half = lane >> 4;     // 0 or 1
    int l16 = lane & 15;
    const uint2* hw2 = (const uint2*)hw16;  // row = 16 uint2
    float4 acc = make_float4(0.f, 0.f, 0.f, 0.f);
    if (half == 0) {
        float di = g_dinv[node];
        float ws = di * di;
        uint2 u = hw2[(size_t)node * 16 + l16];
        float2 f0 = __half22float2(*(const __half2*)&u.x);
        float2 f1 = __half22float2(*(const __half2*)&u.y);
        acc.x = ws * f0.x; acc.y = ws * f0.y; acc.z = ws * f1.x; acc.w = ws * f1.y;
    }
    int s0 = g_rowptr[node], s1 = g_rowptr[node + 1];
    for (int e = s0; e < s1; e += 2) {
        int ee = e + half;
        int2 m = (ee < s1) ? g_csr[ee] : make_int2(0, 0);  // pad: w = 0.0f
        float w = __int_as_float(m.y);
        uint2 u = hw2[(size_t)m.x * 16 + l16];
        float2 f0 = __half22float2(*(const __half2*)&u.x);
        float2 f1 = __half22float2(*(const __half2*)&u.y);
        acc.x = fmaf(w, f0.x, acc.x);
        acc.y = fmaf(w, f0.y, acc.y);
        acc.z = fmaf(w, f1.x, acc.z);
        acc.w = fmaf(w, f1.y, acc.w);
    }
    acc.x += __shfl_down_sync(0xffffffffu, acc.x, 16);
    acc.y += __shfl_down_sync(0xffffffffu, acc.y, 16);
    acc.z += __shfl_down_sync(0xffffffffu, acc.z, 16);
    acc.w += __shfl_down_sync(0xffffffffu, acc.w, 16);
    if (half == 0) {
        float4 bb = ((const float4*)bias)[l16];
        acc.x += bb.x; acc.y += bb.y; acc.z += bb.z; acc.w += bb.w;
        acc.x = acc.x > 0.f ? acc.x : expm1f(acc.x);
        acc.y = acc.y > 0.f ? acc.y : expm1f(acc.y);
        acc.z = acc.z > 0.f ? acc.z : expm1f(acc.z);
        acc.w = acc.w > 0.f ? acc.w : expm1f(acc.w);
        ((float4*)g_h)[(size_t)node * 16 + l16] = acc;
    }
}

// ---------------- final linear 64->32 + bias + ReLU (proven) ----------------
__global__ __launch_bounds__(256) void final_gemm_kernel(
    const float* __restrict__ A, const float* __restrict__ W,
    const float* __restrict__ bias, float* __restrict__ C) {
    constexpr int AP = 68;
    __shared__ float As[64 * AP];
    __shared__ float Ws[64 * OUT_DIM];
    int tid = threadIdx.x;
    int tx = tid & 15, ty = tid >> 4;
    int row0 = blockIdx.x * 64;
    unsigned long long acc[4];
#pragma unroll
    for (int r = 0; r < 4; r++) acc[r] = 0ULL;
    for (int i = tid; i < 64 * 64; i += 256) {
        int r = i >> 6, k = i & 63;
        As[k * AP + r] = A[(size_t)(row0 + r) * 64 + k];
    }
    for (int i = tid; i < 64 * OUT_DIM; i += 256) {
        int k = i / OUT_DIM, c = i % OUT_DIM;
        Ws[k * OUT_DIM + c] = W[(size_t)k * OUT_DIM + c];
    }
    __syncthreads();
#pragma unroll 8
    for (int k = 0; k < 64; k++) {
        float4 a = *(const float4*)&As[k * AP + ty * 4];
        unsigned long long a0 = pk2(a.x, a.x), a1 = pk2(a.y, a.y);
        unsigned long long a2 = pk2(a.z, a.z), a3 = pk2(a.w, a.w);
        float2 w = *(const float2*)&Ws[k * OUT_DIM + tx * 2];
        unsigned long long w01 = pk2(w.x, w.y);
        fma2(acc[0], a0, w01);
        fma2(acc[1], a1, w01);
        fma2(acc[2], a2, w01);
        fma2(acc[3], a3, w01);
    }
#pragma unroll
    for (int r = 0; r < 4; r++) {
        int row = row0 + ty * 4 + r;
        float2 p = unpk(acc[r]);
        p.x += bias[tx * 2];
        p.y += bias[tx * 2 + 1];
        p.x = p.x > 0.f ? p.x : 0.f;
        p.y = p.y > 0.f ? p.y : 0.f;
        *(float2*)&C[(size_t)row * OUT_DIM + tx * 2] = p;
    }
}

// ---------------- launch ----------------
extern "C" void kernel_launch(void* const* d_in, const int* in_sizes, int n_in,
                              void* d_out, int out_size) {
    const float* x      = (const float*)d_in[0];
    const void*  eidx   = d_in[1];
    const float* ew     = (const float*)d_in[2];
    const float* W1     = (const float*)d_in[3];
    const float* b1     = (const float*)d_in[4];
    const float* W_hid  = (const float*)d_in[5];
    const float* b_hid  = (const float*)d_in[6];
    const float* W_lin  = (const float*)d_in[7];
    const float* b_lin  = (const float*)d_in[8];
    float* out = (float*)d_out;

    float* h_ptr;
    __half* hw16_ptr;
    void *count_ptr, *deg_ptr;
    cudaGetSymbolAddress((void**)&h_ptr, g_h);
    cudaGetSymbolAddress((void**)&hw16_ptr, g_hw16);
    cudaGetSymbolAddress(&count_ptr, g_count);
    cudaGetSymbolAddress(&deg_ptr, g_deg);

    // ---- preprocessing + layer-1 GEMM interleaved; launch idx 5 = gemm1 (ncu target) ----
    detect_kernel<<<1, 128>>>((const unsigned int*)eidx);            // 0
    cudaMemsetAsync(count_ptr, 0, N_NODES * sizeof(int));            // 1
    cudaMemsetAsync(deg_ptr, 0, N_NODES * sizeof(float));            // 2
    count_deg_kernel<<<N_EDGES / 256, 256>>>(eidx, ew);              // 3
    chunk_reduce_kernel<<<N_CHUNKS / 8, 256>>>();                    // 4
    gemm_pair_kernel<IN_DIM><<<N_NODES / 64, 256>>>(x, W1, hw16_ptr); // 5 <- profiled
    scan_part_kernel<<<1, N_CHUNKS>>>();                             // 6
    rowptr_dinv_kernel<<<N_CHUNKS / 8, 256>>>();                     // 7
    fill_kernel<<<N_EDGES / 256, 256>>>(eidx, ew);                   // 8

    // ---- layer 1 aggregation ----
    agg_elu_kernel<<<N_NODES / 8, 256>>>(hw16_ptr, b1);              // 9

    // ---- hidden layers: 64 -> 64 ----
    for (int l = 0; l < N_HIDDEN; l++) {
        gemm_pair_kernel<EMB><<<N_NODES / 64, 256>>>(
            h_ptr, W_hid + (size_t)l * EMB * EMB, hw16_ptr);
        agg_elu_kernel<<<N_NODES / 8, 256>>>(hw16_ptr, b_hid + (size_t)l * EMB);
    }

    // ---- final linear 64 -> 32 + bias + ReLU ----
    final_gemm_kernel<<<N_NODES / 64, 256>>>(h_ptr, W_lin, b_lin, out);
}

// round 14
// speedup vs baseline: 1.2403x; 1.0948x over previous
#include <cuda_runtime.h>
#include <cuda_fp16.h>
#include <cstdint>

#define N_NODES 65536
#define N_EDGES 1048576
#define EMB 64
#define IN_DIM 128
#define OUT_DIM 32
#define N_HIDDEN 4
#define N_CHUNKS 1024   // 65536 / 64

// ---------------- scratch (static device globals; no allocation) ----------------
__device__ float  g_h[N_NODES * EMB];        // layer activations (fp32)
__device__ __half g_hw16[N_NODES * EMB];     // post-GEMM messages (fp16 payload)
__device__ float  g_dinv[N_NODES];           // 1/sqrt(deg)
__device__ float  g_deg[N_NODES];            // weighted in-degree (atomic float)
__device__ int    g_count[N_NODES];          // in-degree histogram
__device__ int    g_rowptr[N_NODES + 1];     // CSR row pointers (by dst)
__device__ int    g_work[N_NODES];           // fill cursors (copy of rowptr)
__device__ int2   g_csr[N_EDGES];            // CSR: {src, float_bits(norm_w)}
__device__ int    g_choff[N_CHUNKS];         // exclusive chunk offsets
__device__ int    g_part[N_CHUNKS];          // chunk partial sums
__device__ int    g_is64;                    // edge_index dtype flag

// ---------------- packed f32x2 helpers (Blackwell) ----------------
__device__ __forceinline__ void fma2(unsigned long long& acc,
                                     unsigned long long a, unsigned long long b) {
    asm("fma.rn.f32x2 %0, %1, %2, %0;" : "+l"(acc) : "l"(a), "l"(b));
}
__device__ __forceinline__ unsigned long long pk2(float lo, float hi) {
    unsigned long long r;
    asm("mov.b64 %0, {%1, %2};" : "=l"(r) : "f"(lo), "f"(hi));
    return r;
}
__device__ __forceinline__ float2 unpk(unsigned long long v) {
    float2 f;
    asm("mov.b64 {%0, %1}, %2;" : "=f"(f.x), "=f"(f.y) : "l"(v));
    return f;
}

// ---------------- dtype detection ----------------
__global__ void detect_kernel(const unsigned int* __restrict__ w) {
    __shared__ int s_any;
    if (threadIdx.x == 0) s_any = 0;
    __syncthreads();
    unsigned int v = w[2 * threadIdx.x + 1];
    if (v != 0) s_any = 1;
    __syncthreads();
    if (threadIdx.x == 0) g_is64 = (s_any == 0) ? 1 : 0;
}

__device__ __forceinline__ int load_idx(const void* p, int i) {
    if (g_is64) return (int)((const long long*)p)[i];
    return ((const int*)p)[i];
}

// ---------------- pass 1: count + weighted degree ----------------
__global__ void count_deg_kernel(const void* __restrict__ eidx,
                                 const float* __restrict__ ew) {
    int e = blockIdx.x * blockDim.x + threadIdx.x;
    if (e >= N_EDGES) return;
    int dst = load_idx(eidx, N_EDGES + e);
    atomicAdd(&g_count[dst], 1);
    atomicAdd(&g_deg[dst], ew[e]);
}

// ---------------- scan phase 1 ----------------
__global__ void chunk_reduce_kernel() {
    int warp = (blockIdx.x * blockDim.x + threadIdx.x) >> 5;
    int lane = threadIdx.x & 31;
    if (warp >= N_CHUNKS) return;
    int base = warp * 64;
    int v = g_count[base + lane] + g_count[base + 32 + lane];
#pragma unroll
    for (int off = 16; off > 0; off >>= 1)
        v += __shfl_down_sync(0xffffffffu, v, off);
    if (lane == 0) g_part[warp] = v;
}

// ---------------- scan phase 2 ----------------
__global__ void scan_part_kernel() {
    __shared__ int s[N_CHUNKS];
    int t = threadIdx.x;
    int orig = g_part[t];
    s[t] = orig;
    __syncthreads();
    for (int off = 1; off < N_CHUNKS; off <<= 1) {
        int v = (t >= off) ? s[t - off] : 0;
        __syncthreads();
        s[t] += v;
        __syncthreads();
    }
    g_choff[t] = s[t] - orig;  // exclusive
}

// ---------------- scan phase 3: rowptr + work + dinv ----------------
__global__ void rowptr_dinv_kernel() {
    int warp = (blockIdx.x * blockDim.x + threadIdx.x) >> 5;
    int lane = threadIdx.x & 31;
    if (warp >= N_CHUNKS) return;
    int base = warp * 64;
    int c0 = g_count[base + lane];
    int c1 = g_count[base + 32 + lane];
    int i0 = c0, i1 = c1;
#pragma unroll
    for (int off = 1; off < 32; off <<= 1) {
        int v0 = __shfl_up_sync(0xffffffffu, i0, off);
        int v1 = __shfl_up_sync(0xffffffffu, i1, off);
        if (lane >= off) { i0 += v0; i1 += v1; }
    }
    int tot0 = __shfl_sync(0xffffffffu, i0, 31);
    int off = g_choff[warp];
    int r0 = off + i0 - c0;
    int r1 = off + tot0 + i1 - c1;
    g_rowptr[base + lane] = r0;
    g_rowptr[base + 32 + lane] = r1;
    g_work[base + lane] = r0;
    g_work[base + 32 + lane] = r1;
    if (warp == N_CHUNKS - 1 && lane == 31) g_rowptr[N_NODES] = N_EDGES;
    float d, r;
    d = 1.0f + g_deg[base + lane];
    r = rsqrtf(d);
    g_dinv[base + lane] = r * (1.5f - 0.5f * d * r * r);
    d = 1.0f + g_deg[base + 32 + lane];
    r = rsqrtf(d);
    g_dinv[base + 32 + lane] = r * (1.5f - 0.5f * d * r * r);
}

// ---------------- fill CSR with normalized weights ----------------
__global__ void fill_kernel(const void* __restrict__ eidx,
                            const float* __restrict__ ew) {
    int e = blockIdx.x * blockDim.x + threadIdx.x;
    if (e >= N_EDGES) return;
    int src = load_idx(eidx, e);
    int dst = load_idx(eidx, N_EDGES + e);
    float w = ew[e] * g_dinv[src] * g_dinv[dst];
    int pos = atomicAdd(&g_work[dst], 1);
    g_csr[pos] = make_int2(src, __float_as_int(w));
}

// ---------------- GEMM -> fp16: C16[N_NODES,64] = A[N_NODES,K] @ W[K,64] ----------------
// 128x64 block tile, 256 threads, thread = 8 rows x 4 cols.
// Dynamic smem (51.2KB > 48KB static limit): As[128*68] + Ws2[64*64].
// k-pair f32x2 accumulators; 8-row register tile gives 8-deep independent LDS
// batching per kp (ILP covers latency) and 2x W reuse. A broadcast loads,
// W dedup'd LDS.128, all conflict-free (pad 68).
#define GP8_SMEM_BYTES ((128 * 68 + 64 * 64) * (int)sizeof(float))
template <int K>
__global__ __launch_bounds__(256, 2) void gemm_pair8_kernel(
    const float* __restrict__ A, const float* __restrict__ W,
    __half* __restrict__ C16) {
    extern __shared__ float smem[];
    float* As = smem;                 // 128*68 floats, row-major
    float* Ws2 = smem + 128 * 68;     // 64*64 floats, pair-interleaved
    int tid = threadIdx.x;
    int tx = tid & 15, ty = tid >> 4;
    int row0 = blockIdx.x * 128;

    unsigned long long acc[8][4];
#pragma unroll
    for (int r = 0; r < 8; r++)
#pragma unroll
        for (int c = 0; c < 4; c++) acc[r][c] = 0ULL;

    for (int kc = 0; kc < K; kc += 64) {
        __syncthreads();
        // A tile: 128 rows x 64 floats, float4 loads -> row-major STS (conflict-free)
#pragma unroll
        for (int i = tid; i < 128 * 16; i += 256) {
            int r = i >> 4, f = i & 15;
            float4 v = *(const float4*)&A[(size_t)(row0 + r) * K + kc + f * 4];
            *(float4*)&As[r * 68 + f * 4] = v;
        }
        // W chunk: scatter into pair-interleaved layout
#pragma unroll
        for (int i = tid; i < 64 * 16; i += 256) {
            int k = i >> 4, cg = i & 15;
            float4 v = *(const float4*)&W[(size_t)(kc + k) * 64 + cg * 4];
            int base = (k >> 1) * 128 + (k & 1);
            Ws2[base + (cg * 4 + 0) * 2] = v.x;
            Ws2[base + (cg * 4 + 1) * 2] = v.y;
            Ws2[base + (cg * 4 + 2) * 2] = v.z;
            Ws2[base + (cg * 4 + 3) * 2] = v.w;
        }
        __syncthreads();
#pragma unroll 2
        for (int kp = 0; kp < 32; kp++) {
            ulonglong2 wl = *(const ulonglong2*)&Ws2[kp * 128 + tx * 8];      // cols c0,c1
            ulonglong2 wh = *(const ulonglong2*)&Ws2[kp * 128 + tx * 8 + 4];  // cols c2,c3
#pragma unroll
            for (int r = 0; r < 8; r++) {
                unsigned long long a =
                    *(const unsigned long long*)&As[(ty * 8 + r) * 68 + kp * 2];
                fma2(acc[r][0], a, wl.x);
                fma2(acc[r][1], a, wl.y);
                fma2(acc[r][2], a, wh.x);
                fma2(acc[r][3], a, wh.y);
            }
        }
    }
    // epilogue: fold (even,odd) halves, convert to fp16, one uint2 store per row
#pragma unroll
    for (int r = 0; r < 8; r++) {
        float2 p0 = unpk(acc[r][0]);
        float2 p1 = unpk(acc[r][1]);
        float2 p2 = unpk(acc[r][2]);
        float2 p3 = unpk(acc[r][3]);
        float v0 = p0.x + p0.y, v1 = p1.x + p1.y;
        float v2 = p2.x + p2.y, v3 = p3.x + p3.y;
        int row = row0 + ty * 8 + r;
        __half2 h01 = __floats2half2_rn(v0, v1);
        __half2 h23 = __floats2half2_rn(v2, v3);
        uint2 u;
        u.x = *(unsigned*)&h01;
        u.y = *(unsigned*)&h23;
        ((uint2*)C16)[(size_t)row * 16 + tx] = u;
    }
}

// ---------------- aggregation (fp16 gather) + bias + ELU (R9 version) ----------------
__global__ __launch_bounds__(256) void agg_elu_kernel(
    const __half* __restrict__ hw16, const float* __restrict__ bias) {
    int node = (blockIdx.x * blockDim.x + threadIdx.x) >> 5;
    int lane = threadIdx.x & 31;
    if (node >= N_NODES) return;
    int half = lane >> 4;     // 0 or 1
    int l16 = lane & 15;
    const uint2* hw2 = (const uint2*)hw16;  // row = 16 uint2
    float4 acc = make_float4(0.f, 0.f, 0.f, 0.f);
    if (half == 0) {
        float di = g_dinv[node];
        float ws = di * di;
        uint2 u = hw2[(size_t)node * 16 + l16];
        float2 f0 = __half22float2(*(const __half2*)&u.x);
        float2 f1 = __half22float2(*(const __half2*)&u.y);
        acc.x = ws * f0.x; acc.y = ws * f0.y; acc.z = ws * f1.x; acc.w = ws * f1.y;
    }
    int s0 = g_rowptr[node], s1 = g_rowptr[node + 1];
    for (int e = s0; e < s1; e += 2) {
        int ee = e + half;
        int2 m = (ee < s1) ? g_csr[ee] : make_int2(0, 0);  // pad: w = 0.0f
        float w = __int_as_float(m.y);
        uint2 u = hw2[(size_t)m.x * 16 + l16];
        float2 f0 = __half22float2(*(const __half2*)&u.x);
        float2 f1 = __half22float2(*(const __half2*)&u.y);
        acc.x = fmaf(w, f0.x, acc.x);
        acc.y = fmaf(w, f0.y, acc.y);
        acc.z = fmaf(w, f1.x, acc.z);
        acc.w = fmaf(w, f1.y, acc.w);
    }
    acc.x += __shfl_down_sync(0xffffffffu, acc.x, 16);
    acc.y += __shfl_down_sync(0xffffffffu, acc.y, 16);
    acc.z += __shfl_down_sync(0xffffffffu, acc.z, 16);
    acc.w += __shfl_down_sync(0xffffffffu, acc.w, 16);
    if (half == 0) {
        float4 bb = ((const float4*)bias)[l16];
        acc.x += bb.x; acc.y += bb.y; acc.z += bb.z; acc.w += bb.w;
        acc.x = acc.x > 0.f ? acc.x : expm1f(acc.x);
        acc.y = acc.y > 0.f ? acc.y : expm1f(acc.y);
        acc.z = acc.z > 0.f ? acc.z : expm1f(acc.z);
        acc.w = acc.w > 0.f ? acc.w : expm1f(acc.w);
        ((float4*)g_h)[(size_t)node * 16 + l16] = acc;
    }
}

// ---------------- final linear 64->32 + bias + ReLU (proven) ----------------
__global__ __launch_bounds__(256) void final_gemm_kernel(
    const float* __restrict__ A, const float* __restrict__ W,
    const float* __restrict__ bias, float* __restrict__ C) {
    constexpr int AP = 68;
    __shared__ float As[64 * AP];
    __shared__ float Ws[64 * OUT_DIM];
    int tid = threadIdx.x;
    int tx = tid & 15, ty = tid >> 4;
    int row0 = blockIdx.x * 64;
    unsigned long long acc[4];
#pragma unroll
    for (int r = 0; r < 4; r++) acc[r] = 0ULL;
    for (int i = tid; i < 64 * 64; i += 256) {
        int r = i >> 6, k = i & 63;
        As[k * AP + r] = A[(size_t)(row0 + r) * 64 + k];
    }
    for (int i = tid; i < 64 * OUT_DIM; i += 256) {
        int k = i / OUT_DIM, c = i % OUT_DIM;
        Ws[k * OUT_DIM + c] = W[(size_t)k * OUT_DIM + c];
    }
    __syncthreads();
#pragma unroll 8
    for (int k = 0; k < 64; k++) {
        float4 a = *(const float4*)&As[k * AP + ty * 4];
        unsigned long long a0 = pk2(a.x, a.x), a1 = pk2(a.y, a.y);
        unsigned long long a2 = pk2(a.z, a.z), a3 = pk2(a.w, a.w);
        float2 w = *(const float2*)&Ws[k * OUT_DIM + tx * 2];
        unsigned long long w01 = pk2(w.x, w.y);
        fma2(acc[0], a0, w01);
        fma2(acc[1], a1, w01);
        fma2(acc[2], a2, w01);
        fma2(acc[3], a3, w01);
    }
#pragma unroll
    for (int r = 0; r < 4; r++) {
        int row = row0 + ty * 4 + r;
        float2 p = unpk(acc[r]);
        p.x += bias[tx * 2];
        p.y += bias[tx * 2 + 1];
        p.x = p.x > 0.f ? p.x : 0.f;
        p.y = p.y > 0.f ? p.y : 0.f;
        *(float2*)&C[(size_t)row * OUT_DIM + tx * 2] = p;
    }
}

// ---------------- launch ----------------
extern "C" void kernel_launch(void* const* d_in, const int* in_sizes, int n_in,
                              void* d_out, int out_size) {
    const float* x      = (const float*)d_in[0];
    const void*  eidx   = d_in[1];
    const float* ew     = (const float*)d_in[2];
    const float* W1     = (const float*)d_in[3];
    const float* b1     = (const float*)d_in[4];
    const float* W_hid  = (const float*)d_in[5];
    const float* b_hid  = (const float*)d_in[6];
    const float* W_lin  = (const float*)d_in[7];
    const float* b_lin  = (const float*)d_in[8];
    float* out = (float*)d_out;

    float* h_ptr;
    __half* hw16_ptr;
    void *count_ptr, *deg_ptr;
    cudaGetSymbolAddress((void**)&h_ptr, g_h);
    cudaGetSymbolAddress((void**)&hw16_ptr, g_hw16);
    cudaGetSymbolAddress(&count_ptr, g_count);
    cudaGetSymbolAddress(&deg_ptr, g_deg);

    // raise dynamic-smem cap for the GEMM kernels (attribute set, not an alloc;
    // idempotent, executes immediately even under graph capture)
    cudaFuncSetAttribute(gemm_pair8_kernel<IN_DIM>,
                         cudaFuncAttributeMaxDynamicSharedMemorySize, GP8_SMEM_BYTES);
    cudaFuncSetAttribute(gemm_pair8_kernel<EMB>,
                         cudaFuncAttributeMaxDynamicSharedMemorySize, GP8_SMEM_BYTES);

    // ---- preprocessing + layer-1 GEMM interleaved; launch idx 5 = gemm1 (ncu target) ----
    detect_kernel<<<1, 128>>>((const unsigned int*)eidx);            // 0
    cudaMemsetAsync(count_ptr, 0, N_NODES * sizeof(int));            // 1
    cudaMemsetAsync(deg_ptr, 0, N_NODES * sizeof(float));            // 2
    count_deg_kernel<<<N_EDGES / 256, 256>>>(eidx, ew);              // 3
    chunk_reduce_kernel<<<N_CHUNKS / 8, 256>>>();                    // 4
    gemm_pair8_kernel<IN_DIM><<<N_NODES / 128, 256, GP8_SMEM_BYTES>>>(
        x, W1, hw16_ptr);                                            // 5 <- profiled
    scan_part_kernel<<<1, N_CHUNKS>>>();                             // 6
    rowptr_dinv_kernel<<<N_CHUNKS / 8, 256>>>();                     // 7
    fill_kernel<<<N_EDGES / 256, 256>>>(eidx, ew);                   // 8

    // ---- layer 1 aggregation ----
    agg_elu_kernel<<<N_NODES / 8, 256>>>(hw16_ptr, b1);              // 9

    // ---- hidden layers: 64 -> 64 ----
    for (int l = 0; l < N_HIDDEN; l++) {
        gemm_pair8_kernel<EMB><<<N_NODES / 128, 256, GP8_SMEM_BYTES>>>(
            h_ptr, W_hid + (size_t)l * EMB * EMB, hw16_ptr);
        agg_elu_kernel<<<N_NODES / 8, 256>>>(hw16_ptr, b_hid + (size_t)l * EMB);
    }

    // ---- final linear 64 -> 32 + bias + ReLU ----
    final_gemm_kernel<<<N_NODES / 64, 256>>>(h_ptr, W_lin, b_lin, out);
}

// round 15
// speedup vs baseline: 1.4588x; 1.1762x over previous
#include <cuda_runtime.h>
#include <cuda_fp16.h>
#include <cstdint>

#define N_NODES 65536
#define N_EDGES 1048576
#define EMB 64
#define IN_DIM 128
#define OUT_DIM 32
#define N_HIDDEN 4
#define N_CHUNKS 1024   // 65536 / 64

// ---------------- scratch (static device globals; no allocation) ----------------
__device__ __half g_h16[N_NODES * EMB];      // layer activations (fp16)
__device__ __half g_hw16[N_NODES * EMB];     // post-GEMM messages (fp16)
__device__ float  g_dinv[N_NODES];           // 1/sqrt(deg)
__device__ float  g_deg[N_NODES];            // weighted in-degree (atomic float)
__device__ int    g_count[N_NODES];          // in-degree histogram
__device__ int    g_rowptr[N_NODES + 1];     // CSR row pointers (by dst)
__device__ int    g_work[N_NODES];           // fill cursors (copy of rowptr)
__device__ int2   g_csr[N_EDGES];            // CSR: {src, float_bits(norm_w)}
__device__ int    g_choff[N_CHUNKS];         // exclusive chunk offsets
__device__ int    g_part[N_CHUNKS];          // chunk partial sums
__device__ int    g_is64;                    // edge_index dtype flag

// ---------------- packed f32x2 helpers (Blackwell) ----------------
__device__ __forceinline__ void fma2(unsigned long long& acc,
                                     unsigned long long a, unsigned long long b) {
    asm("fma.rn.f32x2 %0, %1, %2, %0;" : "+l"(acc) : "l"(a), "l"(b));
}
__device__ __forceinline__ unsigned long long pk2(float lo, float hi) {
    unsigned long long r;
    asm("mov.b64 %0, {%1, %2};" : "=l"(r) : "f"(lo), "f"(hi));
    return r;
}
__device__ __forceinline__ float2 unpk(unsigned long long v) {
    float2 f;
    asm("mov.b64 {%0, %1}, %2;" : "=f"(f.x), "=f"(f.y) : "l"(v));
    return f;
}

// ---------------- dtype detection ----------------
__global__ void detect_kernel(const unsigned int* __restrict__ w) {
    __shared__ int s_any;
    if (threadIdx.x == 0) s_any = 0;
    __syncthreads();
    unsigned int v = w[2 * threadIdx.x + 1];
    if (v != 0) s_any = 1;
    __syncthreads();
    if (threadIdx.x == 0) g_is64 = (s_any == 0) ? 1 : 0;
}

__device__ __forceinline__ int load_idx(const void* p, int i) {
    if (g_is64) return (int)((const long long*)p)[i];
    return ((const int*)p)[i];
}

// ---------------- pass 1: count + weighted degree ----------------
__global__ void count_deg_kernel(const void* __restrict__ eidx,
                                 const float* __restrict__ ew) {
    int e = blockIdx.x * blockDim.x + threadIdx.x;
    if (e >= N_EDGES) return;
    int dst = load_idx(eidx, N_EDGES + e);
    atomicAdd(&g_count[dst], 1);
    atomicAdd(&g_deg[dst], ew[e]);
}

// ---------------- scan phase 1 ----------------
__global__ void chunk_reduce_kernel() {
    int warp = (blockIdx.x * blockDim.x + threadIdx.x) >> 5;
    int lane = threadIdx.x & 31;
    if (warp >= N_CHUNKS) return;
    int base = warp * 64;
    int v = g_count[base + lane] + g_count[base + 32 + lane];
#pragma unroll
    for (int off = 16; off > 0; off >>= 1)
        v += __shfl_down_sync(0xffffffffu, v, off);
    if (lane == 0) g_part[warp] = v;
}

// ---------------- scan phase 2 ----------------
__global__ void scan_part_kernel() {
    __shared__ int s[N_CHUNKS];
    int t = threadIdx.x;
    int orig = g_part[t];
    s[t] = orig;
    __syncthreads();
    for (int off = 1; off < N_CHUNKS; off <<= 1) {
        int v = (t >= off) ? s[t - off] : 0;
        __syncthreads();
        s[t] += v;
        __syncthreads();
    }
    g_choff[t] = s[t] - orig;  // exclusive
}

// ---------------- scan phase 3: rowptr + work + dinv ----------------
__global__ void rowptr_dinv_kernel() {
    int warp = (blockIdx.x * blockDim.x + threadIdx.x) >> 5;
    int lane = threadIdx.x & 31;
    if (warp >= N_CHUNKS) return;
    int base = warp * 64;
    int c0 = g_count[base + lane];
    int c1 = g_count[base + 32 + lane];
    int i0 = c0, i1 = c1;
#pragma unroll
    for (int off = 1; off < 32; off <<= 1) {
        int v0 = __shfl_up_sync(0xffffffffu, i0, off);
        int v1 = __shfl_up_sync(0xffffffffu, i1, off);
        if (lane >= off) { i0 += v0; i1 += v1; }
    }
    int tot0 = __shfl_sync(0xffffffffu, i0, 31);
    int off = g_choff[warp];
    int r0 = off + i0 - c0;
    int r1 = off + tot0 + i1 - c1;
    g_rowptr[base + lane] = r0;
    g_rowptr[base + 32 + lane] = r1;
    g_work[base + lane] = r0;
    g_work[base + 32 + lane] = r1;
    if (warp == N_CHUNKS - 1 && lane == 31) g_rowptr[N_NODES] = N_EDGES;
    float d, r;
    d = 1.0f + g_deg[base + lane];
    r = rsqrtf(d);
    g_dinv[base + lane] = r * (1.5f - 0.5f * d * r * r);
    d = 1.0f + g_deg[base + 32 + lane];
    r = rsqrtf(d);
    g_dinv[base + 32 + lane] = r * (1.5f - 0.5f * d * r * r);
}

// ---------------- fill CSR with normalized weights ----------------
__global__ void fill_kernel(const void* __restrict__ eidx,
                            const float* __restrict__ ew) {
    int e = blockIdx.x * blockDim.x + threadIdx.x;
    if (e >= N_EDGES) return;
    int src = load_idx(eidx, e);
    int dst = load_idx(eidx, N_EDGES + e);
    float w = ew[e] * g_dinv[src] * g_dinv[dst];
    int pos = atomicAdd(&g_work[dst], 1);
    g_csr[pos] = make_int2(src, __float_as_int(w));
}

// ---------------- tensor-core GEMM -> fp16: C16 = A @ W ----------------
// mma.sync m16n8k16 f16 inputs, f32 accumulate. 128-row block tile, 8 warps,
// warp = 16 rows x 64 cols (8 n-tiles). A and W^T staged in smem with +8-half
// padding (fragment LDS pattern is conflict-free: word off = 4*(lane/4)+lane%4 mod 32).
// TA=float: converts A (x) to fp16 during staging; TA=__half: direct copy.
#define HMMA_SMEM(K) (192 * ((K) + 8) * 2)
template <typename TA, int K>
__global__ __launch_bounds__(256, 2) void gemm_hmma_kernel(
    const TA* __restrict__ A, const float* __restrict__ W,
    __half* __restrict__ C16) {
    constexpr int SA = K + 8;      // halves per As row
    constexpr int SW = K + 8;      // halves per Wt row
    extern __shared__ __half smh[];
    __half* As = smh;              // [128][SA]
    __half* Wt = smh + 128 * SA;   // [64][SW]  (n-major: Wt[n][k])
    int tid = threadIdx.x;
    int row0 = blockIdx.x * 128;

    // stage A (128 x K halves)
    if (sizeof(TA) == 4) {
        for (int i = tid; i < 128 * (K / 4); i += 256) {
            int r = i / (K / 4), f = i % (K / 4);
            float4 v = *(const float4*)((const float*)A + (size_t)(row0 + r) * K + f * 4);
            __half2 h0 = __floats2half2_rn(v.x, v.y);
            __half2 h1 = __floats2half2_rn(v.z, v.w);
            uint2 u;
            u.x = *(unsigned*)&h0;
            u.y = *(unsigned*)&h1;
            *(uint2*)&As[r * SA + f * 4] = u;
        }
    } else {
        for (int i = tid; i < 128 * (K / 4); i += 256) {
            int r = i / (K / 4), f = i % (K / 4);
            uint2 u = *(const uint2*)((const __half*)A + (size_t)(row0 + r) * K + f * 4);
            *(uint2*)&As[r * SA + f * 4] = u;
        }
    }
    // stage W transposed: Wt[n][k] = (half)W[k][n]
    for (int i = tid; i < K * 16; i += 256) {
        int k = i / 16, cg = i % 16;
        float4 v = *(const float4*)&W[(size_t)k * 64 + cg * 4];
        Wt[(cg * 4 + 0) * SW + k] = __float2half_rn(v.x);
        Wt[(cg * 4 + 1) * SW + k] = __float2half_rn(v.y);
        Wt[(cg * 4 + 2) * SW + k] = __float2half_rn(v.z);
        Wt[(cg * 4 + 3) * SW + k] = __float2half_rn(v.w);
    }
    __syncthreads();

    int warp = tid >> 5, lane = tid & 31;
    int wr = warp * 16;        // warp row offset in tile
    int qr = lane >> 2;        // 0..7
    int qc = (lane & 3) * 2;   // 0,2,4,6
    float acc[8][4];
#pragma unroll
    for (int nt = 0; nt < 8; nt++)
#pragma unroll
        for (int c = 0; c < 4; c++) acc[nt][c] = 0.f;

#pragma unroll
    for (int kc = 0; kc < K; kc += 16) {
        uint32_t a0 = *(const uint32_t*)&As[(wr + qr) * SA + kc + qc];
        uint32_t a1 = *(const uint32_t*)&As[(wr + qr + 8) * SA + kc + qc];
        uint32_t a2 = *(const uint32_t*)&As[(wr + qr) * SA + kc + qc + 8];
        uint32_t a3 = *(const uint32_t*)&As[(wr + qr + 8) * SA + kc + qc + 8];
#pragma unroll
        for (int nt = 0; nt < 8; nt++) {
            uint32_t b0 = *(const uint32_t*)&Wt[(nt * 8 + qr) * SW + kc + qc];
            uint32_t b1 = *(const uint32_t*)&Wt[(nt * 8 + qr) * SW + kc + qc + 8];
            asm volatile(
                "mma.sync.aligned.m16n8k16.row.col.f32.f16.f16.f32 "
                "{%0,%1,%2,%3}, {%4,%5,%6,%7}, {%8,%9}, {%0,%1,%2,%3};"
                : "+f"(acc[nt][0]), "+f"(acc[nt][1]),
                  "+f"(acc[nt][2]), "+f"(acc[nt][3])
                : "r"(a0), "r"(a1), "r"(a2), "r"(a3), "r"(b0), "r"(b1));
        }
    }
    // epilogue: c0/c1 -> (row, n+0/1), c2/c3 -> (row+8, n+0/1)
    int rg = row0 + wr + qr;
#pragma unroll
    for (int nt = 0; nt < 8; nt++) {
        __half2 lo = __floats2half2_rn(acc[nt][0], acc[nt][1]);
        __half2 hi = __floats2half2_rn(acc[nt][2], acc[nt][3]);
        *(__half2*)&C16[(size_t)rg * 64 + nt * 8 + qc] = lo;
        *(__half2*)&C16[(size_t)(rg + 8) * 64 + nt * 8 + qc] = hi;
    }
}

// ---------------- aggregation (fp16 gather) + bias + ELU -> fp16 h ----------------
__global__ __launch_bounds__(256) void agg_elu_kernel(
    const __half* __restrict__ hw16, const float* __restrict__ bias) {
    int node = (blockIdx.x * blockDim.x + threadIdx.x) >> 5;
    int lane = threadIdx.x & 31;
    if (node >= N_NODES) return;
    int half = lane >> 4;     // 0 or 1
    int l16 = lane & 15;
    const uint2* hw2 = (const uint2*)hw16;  // row = 16 uint2
    float4 acc = make_float4(0.f, 0.f, 0.f, 0.f);
    if (half == 0) {
        float di = g_dinv[node];
        float ws = di * di;
        uint2 u = hw2[(size_t)node * 16 + l16];
        float2 f0 = __half22float2(*(const __half2*)&u.x);
        float2 f1 = __half22float2(*(const __half2*)&u.y);
        acc.x = ws * f0.x; acc.y = ws * f0.y; acc.z = ws * f1.x; acc.w = ws * f1.y;
    }
    int s0 = g_rowptr[node], s1 = g_rowptr[node + 1];
    for (int e = s0; e < s1; e += 2) {
        int ee = e + half;
        int2 m = (ee < s1) ? g_csr[ee] : make_int2(0, 0);  // pad: w = 0.0f
        float w = __int_as_float(m.y);
        uint2 u = hw2[(size_t)m.x * 16 + l16];
        float2 f0 = __half22float2(*(const __half2*)&u.x);
        float2 f1 = __half22float2(*(const __half2*)&u.y);
        acc.x = fmaf(w, f0.x, acc.x);
        acc.y = fmaf(w, f0.y, acc.y);
        acc.z = fmaf(w, f1.x, acc.z);
        acc.w = fmaf(w, f1.y, acc.w);
    }
    acc.x += __shfl_down_sync(0xffffffffu, acc.x, 16);
    acc.y += __shfl_down_sync(0xffffffffu, acc.y, 16);
    acc.z += __shfl_down_sync(0xffffffffu, acc.z, 16);
    acc.w += __shfl_down_sync(0xffffffffu, acc.w, 16);
    if (half == 0) {
        float4 bb = ((const float4*)bias)[l16];
        acc.x += bb.x; acc.y += bb.y; acc.z += bb.z; acc.w += bb.w;
        acc.x = acc.x > 0.f ? acc.x : expm1f(acc.x);
        acc.y = acc.y > 0.f ? acc.y : expm1f(acc.y);
        acc.z = acc.z > 0.f ? acc.z : expm1f(acc.z);
        acc.w = acc.w > 0.f ? acc.w : expm1f(acc.w);
        __half2 ha = __floats2half2_rn(acc.x, acc.y);
        __half2 hb = __floats2half2_rn(acc.z, acc.w);
        uint2 u;
        u.x = *(unsigned*)&ha;
        u.y = *(unsigned*)&hb;
        ((uint2*)g_h16)[(size_t)node * 16 + l16] = u;
    }
}

// ---------------- final linear 64->32 + bias + ReLU (f32x2; reads fp16 h) ----------------
__global__ __launch_bounds__(256) void final_gemm_kernel(
    const __half* __restrict__ A16, const float* __restrict__ W,
    const float* __restrict__ bias, float* __restrict__ C) {
    constexpr int AP = 68;
    __shared__ float As[64 * AP];
    __shared__ float Ws[64 * OUT_DIM];
    int tid = threadIdx.x;
    int tx = tid & 15, ty = tid >> 4;
    int row0 = blockIdx.x * 64;
    unsigned long long acc[4];
#pragma unroll
    for (int r = 0; r < 4; r++) acc[r] = 0ULL;
    for (int i = tid; i < 64 * 64; i += 256) {
        int r = i >> 6, k = i & 63;
        As[k * AP + r] = __half2float(A16[(size_t)(row0 + r) * 64 + k]);
    }
    for (int i = tid; i < 64 * OUT_DIM; i += 256) {
        int k = i / OUT_DIM, c = i % OUT_DIM;
        Ws[k * OUT_DIM + c] = W[(size_t)k * OUT_DIM + c];
    }
    __syncthreads();
#pragma unroll 8
    for (int k = 0; k < 64; k++) {
        float4 a = *(const float4*)&As[k * AP + ty * 4];
        unsigned long long a0 = pk2(a.x, a.x), a1 = pk2(a.y, a.y);
        unsigned long long a2 = pk2(a.z, a.z), a3 = pk2(a.w, a.w);
        float2 w = *(const float2*)&Ws[k * OUT_DIM + tx * 2];
        unsigned long long w01 = pk2(w.x, w.y);
        fma2(acc[0], a0, w01);
        fma2(acc[1], a1, w01);
        fma2(acc[2], a2, w01);
        fma2(acc[3], a3, w01);
    }
#pragma unroll
    for (int r = 0; r < 4; r++) {
        int row = row0 + ty * 4 + r;
        float2 p = unpk(acc[r]);
        p.x += bias[tx * 2];
        p.y += bias[tx * 2 + 1];
        p.x = p.x > 0.f ? p.x : 0.f;
        p.y = p.y > 0.f ? p.y : 0.f;
        *(float2*)&C[(size_t)row * OUT_DIM + tx * 2] = p;
    }
}

// ---------------- launch ----------------
extern "C" void kernel_launch(void* const* d_in, const int* in_sizes, int n_in,
                              void* d_out, int out_size) {
    const float* x      = (const float*)d_in[0];
    const void*  eidx   = d_in[1];
    const float* ew     = (const float*)d_in[2];
    const float* W1     = (const float*)d_in[3];
    const float* b1     = (const float*)d_in[4];
    const float* W_hid  = (const float*)d_in[5];
    const float* b_hid  = (const float*)d_in[6];
    const float* W_lin  = (const float*)d_in[7];
    const float* b_lin  = (const float*)d_in[8];
    float* out = (float*)d_out;

    __half *h16_ptr, *hw16_ptr;
    void *count_ptr, *deg_ptr;
    cudaGetSymbolAddress((void**)&h16_ptr, g_h16);
    cudaGetSymbolAddress((void**)&hw16_ptr, g_hw16);
    cudaGetSymbolAddress(&count_ptr, g_count);
    cudaGetSymbolAddress(&deg_ptr, g_deg);

    // raise dynamic-smem caps (attribute set, not an alloc; runs before capture ops)
    cudaFuncSetAttribute(gemm_hmma_kernel<float, IN_DIM>,
                         cudaFuncAttributeMaxDynamicSharedMemorySize, HMMA_SMEM(IN_DIM));
    cudaFuncSetAttribute(gemm_hmma_kernel<__half, EMB>,
                         cudaFuncAttributeMaxDynamicSharedMemorySize, HMMA_SMEM(EMB));

    // ---- preprocessing + layer-1 GEMM interleaved; launch idx 5 = gemm1 (ncu target) ----
    detect_kernel<<<1, 128>>>((const unsigned int*)eidx);            // 0
    cudaMemsetAsync(count_ptr, 0, N_NODES * sizeof(int));            // 1
    cudaMemsetAsync(deg_ptr, 0, N_NODES * sizeof(float));            // 2
    count_deg_kernel<<<N_EDGES / 256, 256>>>(eidx, ew);              // 3
    chunk_reduce_kernel<<<N_CHUNKS / 8, 256>>>();                    // 4
    gemm_hmma_kernel<float, IN_DIM><<<N_NODES / 128, 256, HMMA_SMEM(IN_DIM)>>>(
        x, W1, hw16_ptr);                                            // 5 <- profiled
    scan_part_kernel<<<1, N_CHUNKS>>>();                             // 6
    rowptr_dinv_kernel<<<N_CHUNKS / 8, 256>>>();                     // 7
    fill_kernel<<<N_EDGES / 256, 256>>>(eidx, ew);                   // 8

    // ---- layer 1 aggregation ----
    agg_elu_kernel<<<N_NODES / 8, 256>>>(hw16_ptr, b1);              // 9

    // ---- hidden layers: 64 -> 64 ----
    for (int l = 0; l < N_HIDDEN; l++) {
        gemm_hmma_kernel<__half, EMB><<<N_NODES / 128, 256, HMMA_SMEM(EMB)>>>(
            h16_ptr, W_hid + (size_t)l * EMB * EMB, hw16_ptr);
        agg_elu_kernel<<<N_NODES / 8, 256>>>(hw16_ptr, b_hid + (size_t)l * EMB);
    }

    // ---- final linear 64 -> 32 + bias + ReLU ----
    final_gemm_kernel<<<N_NODES / 64, 256>>>(h16_ptr, W_lin, b_lin, out);
}

// round 16
// speedup vs baseline: 1.4621x; 1.0022x over previous
#include <cuda_runtime.h>
#include <cuda_fp16.h>
#include <cstdint>

#define N_NODES 65536
#define N_EDGES 1048576
#define EMB 64
#define IN_DIM 128
#define OUT_DIM 32
#define N_HIDDEN 4
#define N_CHUNKS 1024   // 65536 / 64

// ---------------- scratch (static device globals; no allocation) ----------------
__device__ __half g_h16[N_NODES * EMB];      // layer activations (fp16)
__device__ __half g_hw16[N_NODES * EMB];     // post-GEMM messages (fp16)
__device__ float  g_dinv[N_NODES];           // 1/sqrt(deg)
__device__ float  g_deg[N_NODES];            // weighted in-degree (atomic float)
__device__ int    g_count[N_NODES];          // in-degree histogram
__device__ int    g_rowptr[N_NODES + 1];     // CSR row pointers (by dst)
__device__ int    g_work[N_NODES];           // fill cursors (copy of rowptr)
__device__ int2   g_csr[N_EDGES];            // CSR: {src, float_bits(norm_w)}
__device__ int    g_choff[N_CHUNKS];         // exclusive chunk offsets
__device__ int    g_part[N_CHUNKS];          // chunk partial sums
__device__ int    g_is64;                    // edge_index dtype flag

// ---------------- packed f32x2 helpers (Blackwell) ----------------
__device__ __forceinline__ void fma2(unsigned long long& acc,
                                     unsigned long long a, unsigned long long b) {
    asm("fma.rn.f32x2 %0, %1, %2, %0;" : "+l"(acc) : "l"(a), "l"(b));
}
__device__ __forceinline__ unsigned long long pk2(float lo, float hi) {
    unsigned long long r;
    asm("mov.b64 %0, {%1, %2};" : "=l"(r) : "f"(lo), "f"(hi));
    return r;
}
__device__ __forceinline__ float2 unpk(unsigned long long v) {
    float2 f;
    asm("mov.b64 {%0, %1}, %2;" : "=f"(f.x), "=f"(f.y) : "l"(v));
    return f;
}

// ---------------- dtype detection ----------------
__global__ void detect_kernel(const unsigned int* __restrict__ w) {
    __shared__ int s_any;
    if (threadIdx.x == 0) s_any = 0;
    __syncthreads();
    unsigned int v = w[2 * threadIdx.x + 1];
    if (v != 0) s_any = 1;
    __syncthreads();
    if (threadIdx.x == 0) g_is64 = (s_any == 0) ? 1 : 0;
}

__device__ __forceinline__ int load_idx(const void* p, int i) {
    if (g_is64) return (int)((const long long*)p)[i];
    return ((const int*)p)[i];
}

// ---------------- pass 1: count + weighted degree ----------------
__global__ void count_deg_kernel(const void* __restrict__ eidx,
                                 const float* __restrict__ ew) {
    int e = blockIdx.x * blockDim.x + threadIdx.x;
    if (e >= N_EDGES) return;
    int dst = load_idx(eidx, N_EDGES + e);
    atomicAdd(&g_count[dst], 1);
    atomicAdd(&g_deg[dst], ew[e]);
}

// ---------------- scan phase 1 ----------------
__global__ void chunk_reduce_kernel() {
    int warp = (blockIdx.x * blockDim.x + threadIdx.x) >> 5;
    int lane = threadIdx.x & 31;
    if (warp >= N_CHUNKS) return;
    int base = warp * 64;
    int v = g_count[base + lane] + g_count[base + 32 + lane];
#pragma unroll
    for (int off = 16; off > 0; off >>= 1)
        v += __shfl_down_sync(0xffffffffu, v, off);
    if (lane == 0) g_part[warp] = v;
}

// ---------------- scan phase 2 ----------------
__global__ void scan_part_kernel() {
    __shared__ int s[N_CHUNKS];
    int t = threadIdx.x;
    int orig = g_part[t];
    s[t] = orig;
    __syncthreads();
    for (int off = 1; off < N_CHUNKS; off <<= 1) {
        int v = (t >= off) ? s[t - off] : 0;
        __syncthreads();
        s[t] += v;
        __syncthreads();
    }
    g_choff[t] = s[t] - orig;  // exclusive
}

// ---------------- scan phase 3: rowptr + work + dinv ----------------
__global__ void rowptr_dinv_kernel() {
    int warp = (blockIdx.x * blockDim.x + threadIdx.x) >> 5;
    int lane = threadIdx.x & 31;
    if (warp >= N_CHUNKS) return;
    int base = warp * 64;
    int c0 = g_count[base + lane];
    int c1 = g_count[base + 32 + lane];
    int i0 = c0, i1 = c1;
#pragma unroll
    for (int off = 1; off < 32; off <<= 1) {
        int v0 = __shfl_up_sync(0xffffffffu, i0, off);
        int v1 = __shfl_up_sync(0xffffffffu, i1, off);
        if (lane >= off) { i0 += v0; i1 += v1; }
    }
    int tot0 = __shfl_sync(0xffffffffu, i0, 31);
    int off = g_choff[warp];
    int r0 = off + i0 - c0;
    int r1 = off + tot0 + i1 - c1;
    g_rowptr[base + lane] = r0;
    g_rowptr[base + 32 + lane] = r1;
    g_work[base + lane] = r0;
    g_work[base + 32 + lane] = r1;
    if (warp == N_CHUNKS - 1 && lane == 31) g_rowptr[N_NODES] = N_EDGES;
    float d, r;
    d = 1.0f + g_deg[base + lane];
    r = rsqrtf(d);
    g_dinv[base + lane] = r * (1.5f - 0.5f * d * r * r);
    d = 1.0f + g_deg[base + 32 + lane];
    r = rsqrtf(d);
    g_dinv[base + 32 + lane] = r * (1.5f - 0.5f * d * r * r);
}

// ---------------- fill CSR with normalized weights ----------------
__global__ void fill_kernel(const void* __restrict__ eidx,
                            const float* __restrict__ ew) {
    int e = blockIdx.x * blockDim.x + threadIdx.x;
    if (e >= N_EDGES) return;
    int src = load_idx(eidx, e);
    int dst = load_idx(eidx, N_EDGES + e);
    float w = ew[e] * g_dinv[src] * g_dinv[dst];
    int pos = atomicAdd(&g_work[dst], 1);
    g_csr[pos] = make_int2(src, __float_as_int(w));
}

// ---------------- tensor-core GEMM -> fp16: C16 = A @ W (R15 proven) ----------------
#define HMMA_SMEM(K) (192 * ((K) + 8) * 2)
template <typename TA, int K>
__global__ __launch_bounds__(256, 2) void gemm_hmma_kernel(
    const TA* __restrict__ A, const float* __restrict__ W,
    __half* __restrict__ C16) {
    constexpr int SA = K + 8;      // halves per As row
    constexpr int SW = K + 8;      // halves per Wt row
    extern __shared__ __half smh[];
    __half* As = smh;              // [128][SA]
    __half* Wt = smh + 128 * SA;   // [64][SW]  (n-major: Wt[n][k])
    int tid = threadIdx.x;
    int row0 = blockIdx.x * 128;

    // stage A (128 x K halves)
    if (sizeof(TA) == 4) {
        for (int i = tid; i < 128 * (K / 4); i += 256) {
            int r = i / (K / 4), f = i % (K / 4);
            float4 v = *(const float4*)((const float*)A + (size_t)(row0 + r) * K + f * 4);
            __half2 h0 = __floats2half2_rn(v.x, v.y);
            __half2 h1 = __floats2half2_rn(v.z, v.w);
            uint2 u;
            u.x = *(unsigned*)&h0;
            u.y = *(unsigned*)&h1;
            *(uint2*)&As[r * SA + f * 4] = u;
        }
    } else {
        for (int i = tid; i < 128 * (K / 4); i += 256) {
            int r = i / (K / 4), f = i % (K / 4);
            uint2 u = *(const uint2*)((const __half*)A + (size_t)(row0 + r) * K + f * 4);
            *(uint2*)&As[r * SA + f * 4] = u;
        }
    }
    // stage W transposed: Wt[n][k] = (half)W[k][n]
    for (int i = tid; i < K * 16; i += 256) {
        int k = i / 16, cg = i % 16;
        float4 v = *(const float4*)&W[(size_t)k * 64 + cg * 4];
        Wt[(cg * 4 + 0) * SW + k] = __float2half_rn(v.x);
        Wt[(cg * 4 + 1) * SW + k] = __float2half_rn(v.y);
        Wt[(cg * 4 + 2) * SW + k] = __float2half_rn(v.z);
        Wt[(cg * 4 + 3) * SW + k] = __float2half_rn(v.w);
    }
    __syncthreads();

    int warp = tid >> 5, lane = tid & 31;
    int wr = warp * 16;        // warp row offset in tile
    int qr = lane >> 2;        // 0..7
    int qc = (lane & 3) * 2;   // 0,2,4,6
    float acc[8][4];
#pragma unroll
    for (int nt = 0; nt < 8; nt++)
#pragma unroll
        for (int c = 0; c < 4; c++) acc[nt][c] = 0.f;

#pragma unroll
    for (int kc = 0; kc < K; kc += 16) {
        uint32_t a0 = *(const uint32_t*)&As[(wr + qr) * SA + kc + qc];
        uint32_t a1 = *(const uint32_t*)&As[(wr + qr + 8) * SA + kc + qc];
        uint32_t a2 = *(const uint32_t*)&As[(wr + qr) * SA + kc + qc + 8];
        uint32_t a3 = *(const uint32_t*)&As[(wr + qr + 8) * SA + kc + qc + 8];
#pragma unroll
        for (int nt = 0; nt < 8; nt++) {
            uint32_t b0 = *(const uint32_t*)&Wt[(nt * 8 + qr) * SW + kc + qc];
            uint32_t b1 = *(const uint32_t*)&Wt[(nt * 8 + qr) * SW + kc + qc + 8];
            asm volatile(
                "mma.sync.aligned.m16n8k16.row.col.f32.f16.f16.f32 "
                "{%0,%1,%2,%3}, {%4,%5,%6,%7}, {%8,%9}, {%0,%1,%2,%3};"
                : "+f"(acc[nt][0]), "+f"(acc[nt][1]),
                  "+f"(acc[nt][2]), "+f"(acc[nt][3])
                : "r"(a0), "r"(a1), "r"(a2), "r"(a3), "r"(b0), "r"(b1));
        }
    }
    // epilogue: c0/c1 -> (row, n+0/1), c2/c3 -> (row+8, n+0/1)
    int rg = row0 + wr + qr;
#pragma unroll
    for (int nt = 0; nt < 8; nt++) {
        __half2 lo = __floats2half2_rn(acc[nt][0], acc[nt][1]);
        __half2 hi = __floats2half2_rn(acc[nt][2], acc[nt][3]);
        *(__half2*)&C16[(size_t)rg * 64 + nt * 8 + qc] = lo;
        *(__half2*)&C16[(size_t)(rg + 8) * 64 + nt * 8 + qc] = hi;
    }
}

// ---------------- aggregation (fp16 gather, MLP-4 batched) + bias + ELU ----------------
// Warp per node. 8 edges per iteration: each half-warp loads meta for 4 edges
// directly (broadcast LDG.64s, predicated; pad w=0), then issues 4 independent
// row gathers (LDG.64/lane, 128B/half-warp), then the FMAs. In-order warp now
// has 4 gathers in flight instead of 1.
__global__ __launch_bounds__(256) void agg_elu_kernel(
    const __half* __restrict__ hw16, const float* __restrict__ bias) {
    int node = (blockIdx.x * blockDim.x + threadIdx.x) >> 5;
    int lane = threadIdx.x & 31;
    if (node >= N_NODES) return;
    int half = lane >> 4;     // 0 or 1
    int l16 = lane & 15;
    const uint2* hw2 = (const uint2*)hw16;  // row = 16 uint2
    float4 acc = make_float4(0.f, 0.f, 0.f, 0.f);
    if (half == 0) {
        float di = g_dinv[node];
        float ws = di * di;
        uint2 u = hw2[(size_t)node * 16 + l16];
        float2 f0 = __half22float2(*(const __half2*)&u.x);
        float2 f1 = __half22float2(*(const __half2*)&u.y);
        acc.x = ws * f0.x; acc.y = ws * f0.y; acc.z = ws * f1.x; acc.w = ws * f1.y;
    }
    int s0 = g_rowptr[node], s1 = g_rowptr[node + 1];
    const int2 pad = make_int2(0, 0);  // src=0, w=0.0f
    for (int e = s0; e < s1; e += 8) {
        int e0 = e + half, e1 = e + 2 + half, e2 = e + 4 + half, e3 = e + 6 + half;
        int2 m0 = (e0 < s1) ? g_csr[e0] : pad;
        int2 m1 = (e1 < s1) ? g_csr[e1] : pad;
        int2 m2 = (e2 < s1) ? g_csr[e2] : pad;
        int2 m3 = (e3 < s1) ? g_csr[e3] : pad;
        uint2 u0 = hw2[(size_t)m0.x * 16 + l16];
        uint2 u1 = hw2[(size_t)m1.x * 16 + l16];
        uint2 u2 = hw2[(size_t)m2.x * 16 + l16];
        uint2 u3 = hw2[(size_t)m3.x * 16 + l16];
        float w0 = __int_as_float(m0.y), w1 = __int_as_float(m1.y);
        float w2 = __int_as_float(m2.y), w3 = __int_as_float(m3.y);
        float2 f;
        f = __half22float2(*(const __half2*)&u0.x);
        acc.x = fmaf(w0, f.x, acc.x); acc.y = fmaf(w0, f.y, acc.y);
        f = __half22float2(*(const __half2*)&u0.y);
        acc.z = fmaf(w0, f.x, acc.z); acc.w = fmaf(w0, f.y, acc.w);
        f = __half22float2(*(const __half2*)&u1.x);
        acc.x = fmaf(w1, f.x, acc.x); acc.y = fmaf(w1, f.y, acc.y);
        f = __half22float2(*(const __half2*)&u1.y);
        acc.z = fmaf(w1, f.x, acc.z); acc.w = fmaf(w1, f.y, acc.w);
        f = __half22float2(*(const __half2*)&u2.x);
        acc.x = fmaf(w2, f.x, acc.x); acc.y = fmaf(w2, f.y, acc.y);
        f = __half22float2(*(const __half2*)&u2.y);
        acc.z = fmaf(w2, f.x, acc.z); acc.w = fmaf(w2, f.y, acc.w);
        f = __half22float2(*(const __half2*)&u3.x);
        acc.x = fmaf(w3, f.x, acc.x); acc.y = fmaf(w3, f.y, acc.y);
        f = __half22float2(*(const __half2*)&u3.y);
        acc.z = fmaf(w3, f.x, acc.z); acc.w = fmaf(w3, f.y, acc.w);
    }
    acc.x += __shfl_down_sync(0xffffffffu, acc.x, 16);
    acc.y += __shfl_down_sync(0xffffffffu, acc.y, 16);
    acc.z += __shfl_down_sync(0xffffffffu, acc.z, 16);
    acc.w += __shfl_down_sync(0xffffffffu, acc.w, 16);
    if (half == 0) {
        float4 bb = ((const float4*)bias)[l16];
        acc.x += bb.x; acc.y += bb.y; acc.z += bb.z; acc.w += bb.w;
        acc.x = acc.x > 0.f ? acc.x : expm1f(acc.x);
        acc.y = acc.y > 0.f ? acc.y : expm1f(acc.y);
        acc.z = acc.z > 0.f ? acc.z : expm1f(acc.z);
        acc.w = acc.w > 0.f ? acc.w : expm1f(acc.w);
        __half2 ha = __floats2half2_rn(acc.x, acc.y);
        __half2 hb = __floats2half2_rn(acc.z, acc.w);
        uint2 u;
        u.x = *(unsigned*)&ha;
        u.y = *(unsigned*)&hb;
        ((uint2*)g_h16)[(size_t)node * 16 + l16] = u;
    }
}

// ---------------- final linear 64->32 + bias + ReLU (f32x2; reads fp16 h) ----------------
__global__ __launch_bounds__(256) void final_gemm_kernel(
    const __half* __restrict__ A16, const float* __restrict__ W,
    const float* __restrict__ bias, float* __restrict__ C) {
    constexpr int AP = 68;
    __shared__ float As[64 * AP];
    __shared__ float Ws[64 * OUT_DIM];
    int tid = threadIdx.x;
    int tx = tid & 15, ty = tid >> 4;
    int row0 = blockIdx.x * 64;
    unsigned long long acc[4];
#pragma unroll
    for (int r = 0; r < 4; r++) acc[r] = 0ULL;
    for (int i = tid; i < 64 * 64; i += 256) {
        int r = i >> 6, k = i & 63;
        As[k * AP + r] = __half2float(A16[(size_t)(row0 + r) * 64 + k]);
    }
    for (int i = tid; i < 64 * OUT_DIM; i += 256) {
        int k = i / OUT_DIM, c = i % OUT_DIM;
        Ws[k * OUT_DIM + c] = W[(size_t)k * OUT_DIM + c];
    }
    __syncthreads();
#pragma unroll 8
    for (int k = 0; k < 64; k++) {
        float4 a = *(const float4*)&As[k * AP + ty * 4];
        unsigned long long a0 = pk2(a.x, a.x), a1 = pk2(a.y, a.y);
        unsigned long long a2 = pk2(a.z, a.z), a3 = pk2(a.w, a.w);
        float2 w = *(const float2*)&Ws[k * OUT_DIM + tx * 2];
        unsigned long long w01 = pk2(w.x, w.y);
        fma2(acc[0], a0, w01);
        fma2(acc[1], a1, w01);
        fma2(acc[2], a2, w01);
        fma2(acc[3], a3, w01);
    }
#pragma unroll
    for (int r = 0; r < 4; r++) {
        int row = row0 + ty * 4 + r;
        float2 p = unpk(acc[r]);
        p.x += bias[tx * 2];
        p.y += bias[tx * 2 + 1];
        p.x = p.x > 0.f ? p.x : 0.f;
        p.y = p.y > 0.f ? p.y : 0.f;
        *(float2*)&C[(size_t)row * OUT_DIM + tx * 2] = p;
    }
}

// ---------------- launch ----------------
extern "C" void kernel_launch(void* const* d_in, const int* in_sizes, int n_in,
                              void* d_out, int out_size) {
    const float* x      = (const float*)d_in[0];
    const void*  eidx   = d_in[1];
    const float* ew     = (const float*)d_in[2];
    const float* W1     = (const float*)d_in[3];
    const float* b1     = (const float*)d_in[4];
    const float* W_hid  = (const float*)d_in[5];
    const float* b_hid  = (const float*)d_in[6];
    const float* W_lin  = (const float*)d_in[7];
    const float* b_lin  = (const float*)d_in[8];
    float* out = (float*)d_out;

    __half *h16_ptr, *hw16_ptr;
    void *count_ptr, *deg_ptr;
    cudaGetSymbolAddress((void**)&h16_ptr, g_h16);
    cudaGetSymbolAddress((void**)&hw16_ptr, g_hw16);
    cudaGetSymbolAddress(&count_ptr, g_count);
    cudaGetSymbolAddress(&deg_ptr, g_deg);

    // raise dynamic-smem caps (attribute set, not an alloc; runs before capture ops)
    cudaFuncSetAttribute(gemm_hmma_kernel<float, IN_DIM>,
                         cudaFuncAttributeMaxDynamicSharedMemorySize, HMMA_SMEM(IN_DIM));
    cudaFuncSetAttribute(gemm_hmma_kernel<__half, EMB>,
                         cudaFuncAttributeMaxDynamicSharedMemorySize, HMMA_SMEM(EMB));

    // ---- preprocessing + layer-1 GEMM interleaved; launch idx 5 = gemm1 (ncu target) ----
    detect_kernel<<<1, 128>>>((const unsigned int*)eidx);            // 0
    cudaMemsetAsync(count_ptr, 0, N_NODES * sizeof(int));            // 1
    cudaMemsetAsync(deg_ptr, 0, N_NODES * sizeof(float));            // 2
    count_deg_kernel<<<N_EDGES / 256, 256>>>(eidx, ew);              // 3
    chunk_reduce_kernel<<<N_CHUNKS / 8, 256>>>();                    // 4
    gemm_hmma_kernel<float, IN_DIM><<<N_NODES / 128, 256, HMMA_SMEM(IN_DIM)>>>(
        x, W1, hw16_ptr);                                            // 5 <- profiled
    scan_part_kernel<<<1, N_CHUNKS>>>();                             // 6
    rowptr_dinv_kernel<<<N_CHUNKS / 8, 256>>>();                     // 7
    fill_kernel<<<N_EDGES / 256, 256>>>(eidx, ew);                   // 8

    // ---- layer 1 aggregation ----
    agg_elu_kernel<<<N_NODES / 8, 256>>>(hw16_ptr, b1);              // 9

    // ---- hidden layers: 64 -> 64 ----
    for (int l = 0; l < N_HIDDEN; l++) {
        gemm_hmma_kernel<__half, EMB><<<N_NODES / 128, 256, HMMA_SMEM(EMB)>>>(
            h16_ptr, W_hid + (size_t)l * EMB * EMB, hw16_ptr);
        agg_elu_kernel<<<N_NODES / 8, 256>>>(hw16_ptr, b_hid + (size_t)l * EMB);
    }

    // ---- final linear 64 -> 32 + bias + ReLU ----
    final_gemm_kernel<<<N_NODES / 64, 256>>>(h16_ptr, W_lin, b_lin, out);
}

// round 17
// speedup vs baseline: 1.4847x; 1.0155x over previous
#include <cuda_runtime.h>
#include <cuda_fp16.h>
#include <cstdint>

#define N_NODES 65536
#define N_EDGES 1048576
#define EMB 64
#define IN_DIM 128
#define OUT_DIM 32
#define N_HIDDEN 4
#define N_CHUNKS 1024   // 65536 / 64

// ---------------- scratch (static device globals; no allocation) ----------------
__device__ __half g_h16[N_NODES * EMB];      // layer activations (fp16)
__device__ __half g_hw16[N_NODES * EMB];     // post-GEMM messages (fp16)
__device__ float  g_dinv[N_NODES];           // 1/sqrt(deg)
__device__ float  g_deg[N_NODES];            // weighted in-degree (atomic float)
__device__ int    g_count[N_NODES];          // in-degree histogram
__device__ int    g_rowptr[N_NODES + 1];     // CSR row pointers (by dst)
__device__ int    g_work[N_NODES];           // fill cursors (copy of rowptr)
__device__ int2   g_csr[N_EDGES];            // CSR: {src, float_bits(norm_w)}
__device__ int    g_choff[N_CHUNKS];         // exclusive chunk offsets
__device__ int    g_part[N_CHUNKS];          // chunk partial sums
__device__ int    g_is64;                    // edge_index dtype flag

// ---------------- packed f32x2 helpers (Blackwell) ----------------
__device__ __forceinline__ void fma2(unsigned long long& acc,
                                     unsigned long long a, unsigned long long b) {
    asm("fma.rn.f32x2 %0, %1, %2, %0;" : "+l"(acc) : "l"(a), "l"(b));
}
__device__ __forceinline__ unsigned long long pk2(float lo, float hi) {
    unsigned long long r;
    asm("mov.b64 %0, {%1, %2};" : "=l"(r) : "f"(lo), "f"(hi));
    return r;
}
__device__ __forceinline__ float2 unpk(unsigned long long v) {
    float2 f;
    asm("mov.b64 {%0, %1}, %2;" : "=f"(f.x), "=f"(f.y) : "l"(v));
    return f;
}

// ---------------- init: zero count/deg + dtype detection (fused) ----------------
// int64 little-endian with values < 2^31 => every odd int32 word is 0.
__global__ void init_kernel(const unsigned int* __restrict__ w) {
    int i = blockIdx.x * blockDim.x + threadIdx.x;   // grid covers N_NODES exactly
    g_count[i] = 0;
    g_deg[i] = 0.f;
    if (blockIdx.x == 0) {
        __shared__ int s_any;
        if (threadIdx.x == 0) s_any = 0;
        __syncthreads();
        if (threadIdx.x < 128) {
            unsigned int v = w[2 * threadIdx.x + 1];  // idx<=255, in-bounds either way
            if (v != 0) s_any = 1;
        }
        __syncthreads();
        if (threadIdx.x == 0) g_is64 = (s_any == 0) ? 1 : 0;
    }
}

__device__ __forceinline__ int load_idx(const void* p, int i) {
    if (g_is64) return (int)((const long long*)p)[i];
    return ((const int*)p)[i];
}

// ---------------- pass 1: count + weighted degree ----------------
__global__ void count_deg_kernel(const void* __restrict__ eidx,
                                 const float* __restrict__ ew) {
    int e = blockIdx.x * blockDim.x + threadIdx.x;
    if (e >= N_EDGES) return;
    int dst = load_idx(eidx, N_EDGES + e);
    atomicAdd(&g_count[dst], 1);
    atomicAdd(&g_deg[dst], ew[e]);
}

// ---------------- scan phase 1 ----------------
__global__ void chunk_reduce_kernel() {
    int warp = (blockIdx.x * blockDim.x + threadIdx.x) >> 5;
    int lane = threadIdx.x & 31;
    if (warp >= N_CHUNKS) return;
    int base = warp * 64;
    int v = g_count[base + lane] + g_count[base + 32 + lane];
#pragma unroll
    for (int off = 16; off > 0; off >>= 1)
        v += __shfl_down_sync(0xffffffffu, v, off);
    if (lane == 0) g_part[warp] = v;
}

// ---------------- scan phase 2 ----------------
__global__ void scan_part_kernel() {
    __shared__ int s[N_CHUNKS];
    int t = threadIdx.x;
    int orig = g_part[t];
    s[t] = orig;
    __syncthreads();
    for (int off = 1; off < N_CHUNKS; off <<= 1) {
        int v = (t >= off) ? s[t - off] : 0;
        __syncthreads();
        s[t] += v;
        __syncthreads();
    }
    g_choff[t] = s[t] - orig;  // exclusive
}

// ---------------- scan phase 3: rowptr + work + dinv ----------------
__global__ void rowptr_dinv_kernel() {
    int warp = (blockIdx.x * blockDim.x + threadIdx.x) >> 5;
    int lane = threadIdx.x & 31;
    if (warp >= N_CHUNKS) return;
    int base = warp * 64;
    int c0 = g_count[base + lane];
    int c1 = g_count[base + 32 + lane];
    int i0 = c0, i1 = c1;
#pragma unroll
    for (int off = 1; off < 32; off <<= 1) {
        int v0 = __shfl_up_sync(0xffffffffu, i0, off);
        int v1 = __shfl_up_sync(0xffffffffu, i1, off);
        if (lane >= off) { i0 += v0; i1 += v1; }
    }
    int tot0 = __shfl_sync(0xffffffffu, i0, 31);
    int off = g_choff[warp];
    int r0 = off + i0 - c0;
    int r1 = off + tot0 + i1 - c1;
    g_rowptr[base + lane] = r0;
    g_rowptr[base + 32 + lane] = r1;
    g_work[base + lane] = r0;
    g_work[base + 32 + lane] = r1;
    if (warp == N_CHUNKS - 1 && lane == 31) g_rowptr[N_NODES] = N_EDGES;
    float d, r;
    d = 1.0f + g_deg[base + lane];
    r = rsqrtf(d);
    g_dinv[base + lane] = r * (1.5f - 0.5f * d * r * r);
    d = 1.0f + g_deg[base + 32 + lane];
    r = rsqrtf(d);
    g_dinv[base + 32 + lane] = r * (1.5f - 0.5f * d * r * r);
}

// ---------------- fill CSR with normalized weights ----------------
__global__ void fill_kernel(const void* __restrict__ eidx,
                            const float* __restrict__ ew) {
    int e = blockIdx.x * blockDim.x + threadIdx.x;
    if (e >= N_EDGES) return;
    int src = load_idx(eidx, e);
    int dst = load_idx(eidx, N_EDGES + e);
    float w = ew[e] * g_dinv[src] * g_dinv[dst];
    int pos = atomicAdd(&g_work[dst], 1);
    g_csr[pos] = make_int2(src, __float_as_int(w));
}

// ---------------- tensor-core GEMM -> fp16: C16 = A @ W ----------------
#define HMMA_SMEM(K) (192 * ((K) + 8) * 2)
template <typename TA, int K>
__global__ __launch_bounds__(256, 3) void gemm_hmma_kernel(
    const TA* __restrict__ A, const float* __restrict__ W,
    __half* __restrict__ C16) {
    constexpr int SA = K + 8;      // halves per As row
    constexpr int SW = K + 8;      // halves per Wt row
    extern __shared__ __half smh[];
    __half* As = smh;              // [128][SA]
    __half* Wt = smh + 128 * SA;   // [64][SW]  (n-major: Wt[n][k])
    int tid = threadIdx.x;
    int row0 = blockIdx.x * 128;

    // stage A (128 x K halves)
    if (sizeof(TA) == 4) {
        for (int i = tid; i < 128 * (K / 4); i += 256) {
            int r = i / (K / 4), f = i % (K / 4);
            float4 v = *(const float4*)((const float*)A + (size_t)(row0 + r) * K + f * 4);
            __half2 h0 = __floats2half2_rn(v.x, v.y);
            __half2 h1 = __floats2half2_rn(v.z, v.w);
            uint2 u;
            u.x = *(unsigned*)&h0;
            u.y = *(unsigned*)&h1;
            *(uint2*)&As[r * SA + f * 4] = u;
        }
    } else {
        for (int i = tid; i < 128 * (K / 4); i += 256) {
            int r = i / (K / 4), f = i % (K / 4);
            uint2 u = *(const uint2*)((const __half*)A + (size_t)(row0 + r) * K + f * 4);
            *(uint2*)&As[r * SA + f * 4] = u;
        }
    }
    // stage W transposed: Wt[n][k] = (half)W[k][n]
    for (int i = tid; i < K * 16; i += 256) {
        int k = i / 16, cg = i % 16;
        float4 v = *(const float4*)&W[(size_t)k * 64 + cg * 4];
        Wt[(cg * 4 + 0) * SW + k] = __float2half_rn(v.x);
        Wt[(cg * 4 + 1) * SW + k] = __float2half_rn(v.y);
        Wt[(cg * 4 + 2) * SW + k] = __float2half_rn(v.z);
        Wt[(cg * 4 + 3) * SW + k] = __float2half_rn(v.w);
    }
    __syncthreads();

    int warp = tid >> 5, lane = tid & 31;
    int wr = warp * 16;        // warp row offset in tile
    int qr = lane >> 2;        // 0..7
    int qc = (lane & 3) * 2;   // 0,2,4,6
    float acc[8][4];
#pragma unroll
    for (int nt = 0; nt < 8; nt++)
#pragma unroll
        for (int c = 0; c < 4; c++) acc[nt][c] = 0.f;

#pragma unroll
    for (int kc = 0; kc < K; kc += 16) {
        uint32_t a0 = *(const uint32_t*)&As[(wr + qr) * SA + kc + qc];
        uint32_t a1 = *(const uint32_t*)&As[(wr + qr + 8) * SA + kc + qc];
        uint32_t a2 = *(const uint32_t*)&As[(wr + qr) * SA + kc + qc + 8];
        uint32_t a3 = *(const uint32_t*)&As[(wr + qr + 8) * SA + kc + qc + 8];
#pragma unroll
        for (int nt = 0; nt < 8; nt++) {
            uint32_t b0 = *(const uint32_t*)&Wt[(nt * 8 + qr) * SW + kc + qc];
            uint32_t b1 = *(const uint32_t*)&Wt[(nt * 8 + qr) * SW + kc + qc + 8];
            asm volatile(
                "mma.sync.aligned.m16n8k16.row.col.f32.f16.f16.f32 "
                "{%0,%1,%2,%3}, {%4,%5,%6,%7}, {%8,%9}, {%0,%1,%2,%3};"
                : "+f"(acc[nt][0]), "+f"(acc[nt][1]),
                  "+f"(acc[nt][2]), "+f"(acc[nt][3])
                : "r"(a0), "r"(a1), "r"(a2), "r"(a3), "r"(b0), "r"(b1));
        }
    }
    // epilogue: c0/c1 -> (row, n+0/1), c2/c3 -> (row+8, n+0/1)
    int rg = row0 + wr + qr;
#pragma unroll
    for (int nt = 0; nt < 8; nt++) {
        __half2 lo = __floats2half2_rn(acc[nt][0], acc[nt][1]);
        __half2 hi = __floats2half2_rn(acc[nt][2], acc[nt][3]);
        *(__half2*)&C16[(size_t)rg * 64 + nt * 8 + qc] = lo;
        *(__half2*)&C16[(size_t)(rg + 8) * 64 + nt * 8 + qc] = hi;
    }
}

// ---------------- aggregation (fp16 gather, MLP-4 batched) + bias + ELU ----------------
__global__ __launch_bounds__(256) void agg_elu_kernel(
    const __half* __restrict__ hw16, const float* __restrict__ bias) {
    int node = (blockIdx.x * blockDim.x + threadIdx.x) >> 5;
    int lane = threadIdx.x & 31;
    if (node >= N_NODES) return;
    int half = lane >> 4;     // 0 or 1
    int l16 = lane & 15;
    const uint2* hw2 = (const uint2*)hw16;  // row = 16 uint2
    float4 acc = make_float4(0.f, 0.f, 0.f, 0.f);
    if (half == 0) {
        float di = g_dinv[node];
        float ws = di * di;
        uint2 u = hw2[(size_t)node * 16 + l16];
        float2 f0 = __half22float2(*(const __half2*)&u.x);
        float2 f1 = __half22float2(*(const __half2*)&u.y);
        acc.x = ws * f0.x; acc.y = ws * f0.y; acc.z = ws * f1.x; acc.w = ws * f1.y;
    }
    int s0 = g_rowptr[node], s1 = g_rowptr[node + 1];
    const int2 pad = make_int2(0, 0);  // src=0, w=0.0f
    for (int e = s0; e < s1; e += 8) {
        int e0 = e + half, e1 = e + 2 + half, e2 = e + 4 + half, e3 = e + 6 + half;
        int2 m0 = (e0 < s1) ? g_csr[e0] : pad;
        int2 m1 = (e1 < s1) ? g_csr[e1] : pad;
        int2 m2 = (e2 < s1) ? g_csr[e2] : pad;
        int2 m3 = (e3 < s1) ? g_csr[e3] : pad;
        uint2 u0 = hw2[(size_t)m0.x * 16 + l16];
        uint2 u1 = hw2[(size_t)m1.x * 16 + l16];
        uint2 u2 = hw2[(size_t)m2.x * 16 + l16];
        uint2 u3 = hw2[(size_t)m3.x * 16 + l16];
        float w0 = __int_as_float(m0.y), w1 = __int_as_float(m1.y);
        float w2 = __int_as_float(m2.y), w3 = __int_as_float(m3.y);
        float2 f;
        f = __half22float2(*(const __half2*)&u0.x);
        acc.x = fmaf(w0, f.x, acc.x); acc.y = fmaf(w0, f.y, acc.y);
        f = __half22float2(*(const __half2*)&u0.y);
        acc.z = fmaf(w0, f.x, acc.z); acc.w = fmaf(w0, f.y, acc.w);
        f = __half22float2(*(const __half2*)&u1.x);
        acc.x = fmaf(w1, f.x, acc.x); acc.y = fmaf(w1, f.y, acc.y);
        f = __half22float2(*(const __half2*)&u1.y);
        acc.z = fmaf(w1, f.x, acc.z); acc.w = fmaf(w1, f.y, acc.w);
        f = __half22float2(*(const __half2*)&u2.x);
        acc.x = fmaf(w2, f.x, acc.x); acc.y = fmaf(w2, f.y, acc.y);
        f = __half22float2(*(const __half2*)&u2.y);
        acc.z = fmaf(w2, f.x, acc.z); acc.w = fmaf(w2, f.y, acc.w);
        f = __half22float2(*(const __half2*)&u3.x);
        acc.x = fmaf(w3, f.x, acc.x); acc.y = fmaf(w3, f.y, acc.y);
        f = __half22float2(*(const __half2*)&u3.y);
        acc.z = fmaf(w3, f.x, acc.z); acc.w = fmaf(w3, f.y, acc.w);
    }
    acc.x += __shfl_down_sync(0xffffffffu, acc.x, 16);
    acc.y += __shfl_down_sync(0xffffffffu, acc.y, 16);
    acc.z += __shfl_down_sync(0xffffffffu, acc.z, 16);
    acc.w += __shfl_down_sync(0xffffffffu, acc.w, 16);
    if (half == 0) {
        float4 bb = ((const float4*)bias)[l16];
        acc.x += bb.x; acc.y += bb.y; acc.z += bb.z; acc.w += bb.w;
        acc.x = acc.x > 0.f ? acc.x : expm1f(acc.x);
        acc.y = acc.y > 0.f ? acc.y : expm1f(acc.y);
        acc.z = acc.z > 0.f ? acc.z : expm1f(acc.z);
        acc.w = acc.w > 0.f ? acc.w : expm1f(acc.w);
        __half2 ha = __floats2half2_rn(acc.x, acc.y);
        __half2 hb = __floats2half2_rn(acc.z, acc.w);
        uint2 u;
        u.x = *(unsigned*)&ha;
        u.y = *(unsigned*)&hb;
        ((uint2*)g_h16)[(size_t)node * 16 + l16] = u;
    }
}

// ---------------- final linear 64->32 + bias + ReLU (f32x2; reads fp16 h) ----------------
__global__ __launch_bounds__(256) void final_gemm_kernel(
    const __half* __restrict__ A16, const float* __restrict__ W,
    const float* __restrict__ bias, float* __restrict__ C) {
    constexpr int AP = 68;
    __shared__ float As[64 * AP];
    __shared__ float Ws[64 * OUT_DIM];
    int tid = threadIdx.x;
    int tx = tid & 15, ty = tid >> 4;
    int row0 = blockIdx.x * 64;
    unsigned long long acc[4];
#pragma unroll
    for (int r = 0; r < 4; r++) acc[r] = 0ULL;
    for (int i = tid; i < 64 * 64; i += 256) {
        int r = i >> 6, k = i & 63;
        As[k * AP + r] = __half2float(A16[(size_t)(row0 + r) * 64 + k]);
    }
    for (int i = tid; i < 64 * OUT_DIM; i += 256) {
        int k = i / OUT_DIM, c = i % OUT_DIM;
        Ws[k * OUT_DIM + c] = W[(size_t)k * OUT_DIM + c];
    }
    __syncthreads();
#pragma unroll 8
    for (int k = 0; k < 64; k++) {
        float4 a = *(const float4*)&As[k * AP + ty * 4];
        unsigned long long a0 = pk2(a.x, a.x), a1 = pk2(a.y, a.y);
        unsigned long long a2 = pk2(a.z, a.z), a3 = pk2(a.w, a.w);
        float2 w = *(const float2*)&Ws[k * OUT_DIM + tx * 2];
        unsigned long long w01 = pk2(w.x, w.y);
        fma2(acc[0], a0, w01);
        fma2(acc[1], a1, w01);
        fma2(acc[2], a2, w01);
        fma2(acc[3], a3, w01);
    }
#pragma unroll
    for (int r = 0; r < 4; r++) {
        int row = row0 + ty * 4 + r;
        float2 p = unpk(acc[r]);
        p.x += bias[tx * 2];
        p.y += bias[tx * 2 + 1];
        p.x = p.x > 0.f ? p.x : 0.f;
        p.y = p.y > 0.f ? p.y : 0.f;
        *(float2*)&C[(size_t)row * OUT_DIM + tx * 2] = p;
    }
}

// ---------------- launch ----------------
extern "C" void kernel_launch(void* const* d_in, const int* in_sizes, int n_in,
                              void* d_out, int out_size) {
    const float* x      = (const float*)d_in[0];
    const void*  eidx   = d_in[1];
    const float* ew     = (const float*)d_in[2];
    const float* W1     = (const float*)d_in[3];
    const float* b1     = (const float*)d_in[4];
    const float* W_hid  = (const float*)d_in[5];
    const float* b_hid  = (const float*)d_in[6];
    const float* W_lin  = (const float*)d_in[7];
    const float* b_lin  = (const float*)d_in[8];
    float* out = (float*)d_out;

    __half *h16_ptr, *hw16_ptr;
    cudaGetSymbolAddress((void**)&h16_ptr, g_h16);
    cudaGetSymbolAddress((void**)&hw16_ptr, g_hw16);

    // raise dynamic-smem caps (attribute set, not an alloc; runs before capture ops)
    cudaFuncSetAttribute(gemm_hmma_kernel<float, IN_DIM>,
                         cudaFuncAttributeMaxDynamicSharedMemorySize, HMMA_SMEM(IN_DIM));
    cudaFuncSetAttribute(gemm_hmma_kernel<__half, EMB>,
                         cudaFuncAttributeMaxDynamicSharedMemorySize, HMMA_SMEM(EMB));

    // ---- preprocessing; launch idx 5 = fill_kernel (ncu target this round) ----
    init_kernel<<<N_NODES / 256, 256>>>((const unsigned int*)eidx);  // 0
    count_deg_kernel<<<N_EDGES / 256, 256>>>(eidx, ew);              // 1
    chunk_reduce_kernel<<<N_CHUNKS / 8, 256>>>();                    // 2
    scan_part_kernel<<<1, N_CHUNKS>>>();                             // 3
    rowptr_dinv_kernel<<<N_CHUNKS / 8, 256>>>();                     // 4
    fill_kernel<<<N_EDGES / 256, 256>>>(eidx, ew);                   // 5 <- profiled
    gemm_hmma_kernel<float, IN_DIM><<<N_NODES / 128, 256, HMMA_SMEM(IN_DIM)>>>(
        x, W1, hw16_ptr);                                            // 6

    // ---- layer 1 aggregation ----
    agg_elu_kernel<<<N_NODES / 8, 256>>>(hw16_ptr, b1);              // 7

    // ---- hidden layers: 64 -> 64 ----
    for (int l = 0; l < N_HIDDEN; l++) {
        gemm_hmma_kernel<__half, EMB><<<N_NODES / 128, 256, HMMA_SMEM(EMB)>>>(
            h16_ptr, W_hid + (size_t)l * EMB * EMB, hw16_ptr);
        agg_elu_kernel<<<N_NODES / 8, 256>>>(hw16_ptr, b_hid + (size_t)l * EMB);
    }

    // ---- final linear 64 -> 32 + bias + ReLU ----
    final_gemm_kernel<<<N_NODES / 64, 256>>>(h16_ptr, W_lin, b_lin, out);
}